// round 1
// baseline (speedup 1.0000x reference)
#include <cuda_runtime.h>
#include <math.h>

// Problem shape (fixed by the reference).
#define B_ 8
#define T_ 2048
#define C_ 1024
#define H_ 128
#define M_ (B_ * T_)   // 16384 rows for the projection GEMM

// Scratch for q/k/v (no cudaMalloc allowed -> __device__ globals). 3 x 8 MB.
__device__ float g_q[(size_t)M_ * H_];
__device__ float g_k[(size_t)M_ * H_];
__device__ float g_v[(size_t)M_ * H_];

// ---------------------------------------------------------------------------
// Kernel 1: QKV projection.  Y = X @ W,  X:[16384,1024], W:[1024,128].
// Grid (M_/64, 3): blockIdx.y selects Wk/Wq/Wv.  256 threads.
// Block tile 64x128, K-step 32. Thread (tx=tid&31, ty=tid>>5) computes an
// 8x4 register tile: rows ty*8..+7, cols tx*4..+3.
// ---------------------------------------------------------------------------
__global__ __launch_bounds__(256) void proj_kernel(
    const float* __restrict__ x,
    const float* __restrict__ Wk,
    const float* __restrict__ Wq,
    const float* __restrict__ Wv)
{
    __shared__ float Xs[64][36];    // padded: stride 36 floats (16B multiple)
    __shared__ float Ws[32][128];

    const float* W;
    float* out;
    if (blockIdx.y == 0)      { W = Wk; out = g_k; }
    else if (blockIdx.y == 1) { W = Wq; out = g_q; }
    else                      { W = Wv; out = g_v; }

    const int row0 = blockIdx.x * 64;
    const int tid  = threadIdx.x;
    const int tx   = tid & 31;   // col group
    const int ty   = tid >> 5;   // row group (== warp id -> Xs reads broadcast)

    float acc[8][4];
#pragma unroll
    for (int i = 0; i < 8; i++)
#pragma unroll
        for (int j = 0; j < 4; j++) acc[i][j] = 0.f;

    for (int k0 = 0; k0 < C_; k0 += 32) {
        // X tile: 64 rows x 32 k = 512 float4, 2 per thread, coalesced.
#pragma unroll
        for (int i = 0; i < 2; i++) {
            int idx = tid + 256 * i;
            int r = idx >> 3, k4 = idx & 7;
            float4 v = *(const float4*)(x + (size_t)(row0 + r) * C_ + k0 + k4 * 4);
            *(float4*)(&Xs[r][k4 * 4]) = v;
        }
        // W tile: 32 x 128 = 1024 float4, 4 per thread, coalesced.
#pragma unroll
        for (int i = 0; i < 4; i++) {
            int idx = tid + 256 * i;
            int kr = idx >> 5, c4 = idx & 31;
            *(float4*)(&Ws[kr][c4 * 4]) =
                *(const float4*)(W + (size_t)(k0 + kr) * H_ + c4 * 4);
        }
        __syncthreads();

#pragma unroll
        for (int kk = 0; kk < 32; kk++) {
            float4 b = *(const float4*)(&Ws[kk][tx * 4]);   // conflict-free
#pragma unroll
            for (int i = 0; i < 8; i++) {
                float a = Xs[ty * 8 + i][kk];               // warp broadcast
                acc[i][0] += a * b.x;
                acc[i][1] += a * b.y;
                acc[i][2] += a * b.z;
                acc[i][3] += a * b.w;
            }
        }
        __syncthreads();
    }

#pragma unroll
    for (int i = 0; i < 8; i++) {
        float4 v = make_float4(acc[i][0], acc[i][1], acc[i][2], acc[i][3]);
        *(float4*)(out + (size_t)(row0 + ty * 8 + i) * H_ + tx * 4) = v;
    }
}

// ---------------------------------------------------------------------------
// Kernel 2: causal flash attention.
// Grid (T_/64, B_), 256 threads. Br = Bc = 64, head dim 128.
// Thread (tx=tid&15, ty=tid>>4):
//   - score tile S: rows ty*4..+3, cols tx*4..+3 (4x4)
//   - output tile O: rows ty*4..+3, cols {tx*4..+3, 64+tx*4..+3} (4x8)
// Online softmax stats (m,l) per row, replicated across the 16 tx lanes via
// width-16 shuffle reductions (offsets 8..1 stay inside the half-warp group).
// ---------------------------------------------------------------------------
#define QS_STRIDE 132   // 64 x 132 floats  (pad -> ty-pair reads hit distinct banks)
#define KT_STRIDE 65    // 128 x 65 floats  (K transposed: Kst[h][c])
#define VS_STRIDE 128   // 64 x 128 floats
#define PS_STRIDE 68    // 64 x 68 floats   (68*4B = 272B, 16B multiple)
#define ATTN_SMEM ((64 * QS_STRIDE + 128 * KT_STRIDE + 64 * VS_STRIDE + 64 * PS_STRIDE) * 4)

__global__ __launch_bounds__(256) void attn_kernel(float* __restrict__ out)
{
    extern __shared__ float sm[];
    float* Qs  = sm;                          // [64][132]
    float* Kst = Qs + 64 * QS_STRIDE;         // [128][65]
    float* Vs  = Kst + 128 * KT_STRIDE;       // [64][128]
    float* Ps  = Vs + 64 * VS_STRIDE;         // [64][68]

    const int b   = blockIdx.y;
    const int qt  = blockIdx.x;
    const int q0  = qt * 64;
    const int tid = threadIdx.x;
    const int tx  = tid & 15;
    const int ty  = tid >> 4;

    // Load Q tile, pre-scaled by C^-0.5 = 1/32 (reference scales by n_embed).
    const float* qg = g_q + ((size_t)b * T_ + q0) * H_;
#pragma unroll
    for (int i = 0; i < 8; i++) {
        int idx = tid + 256 * i;           // 2048 float4
        int r = idx >> 5, h4 = idx & 31;
        float4 v = *(const float4*)(qg + (size_t)r * H_ + h4 * 4);
        v.x *= 0.03125f; v.y *= 0.03125f; v.z *= 0.03125f; v.w *= 0.03125f;
        *(float4*)(&Qs[r * QS_STRIDE + h4 * 4]) = v;
    }

    float m[4], l[4], o[4][8];
#pragma unroll
    for (int i = 0; i < 4; i++) {
        m[i] = -1e30f; l[i] = 0.f;
#pragma unroll
        for (int j = 0; j < 8; j++) o[i][j] = 0.f;
    }

    for (int j = 0; j <= qt; j++) {
        const int kv0 = j * 64;
        const float* kg = g_k + ((size_t)b * T_ + kv0) * H_;
        const float* vg = g_v + ((size_t)b * T_ + kv0) * H_;

        __syncthreads();   // previous iteration done reading Vs/Ps

        // K tile transposed into Kst[h][c] (coalesced gmem read; 4-way smem
        // write conflict is confined to this copy).
        {
            int h4 = tid & 31;
            int cb = tid >> 5;
#pragma unroll
            for (int cc = 0; cc < 8; cc++) {
                int c = cb + cc * 8;
                float4 kv = *(const float4*)(kg + (size_t)c * H_ + h4 * 4);
                Kst[(h4 * 4 + 0) * KT_STRIDE + c] = kv.x;
                Kst[(h4 * 4 + 1) * KT_STRIDE + c] = kv.y;
                Kst[(h4 * 4 + 2) * KT_STRIDE + c] = kv.z;
                Kst[(h4 * 4 + 3) * KT_STRIDE + c] = kv.w;
            }
        }
        // V tile (layout matches gmem; plain coalesced copy).
#pragma unroll
        for (int i = 0; i < 8; i++) {
            int idx = tid + 256 * i;
            int r = idx >> 5, h4 = idx & 31;
            *(float4*)(&Vs[r * VS_STRIDE + h4 * 4]) =
                *(const float4*)(vg + (size_t)r * H_ + h4 * 4);
        }
        __syncthreads();

        // S = (Q/32) @ K^T, 4x4 per thread.
        float s[4][4];
#pragma unroll
        for (int i = 0; i < 4; i++)
#pragma unroll
            for (int jj = 0; jj < 4; jj++) s[i][jj] = 0.f;

#pragma unroll 4
        for (int h = 0; h < 128; h++) {
            float qv[4], kv[4];
#pragma unroll
            for (int i = 0; i < 4; i++)
                qv[i] = Qs[(ty * 4 + i) * QS_STRIDE + h];      // conflict-free
#pragma unroll
            for (int jj = 0; jj < 4; jj++)
                kv[jj] = Kst[h * KT_STRIDE + tx * 4 + jj];     // 2-way worst
#pragma unroll
            for (int i = 0; i < 4; i++)
#pragma unroll
                for (int jj = 0; jj < 4; jj++)
                    s[i][jj] += qv[i] * kv[jj];
        }

        // Causal mask only needed on the diagonal tile (kv0 == q0).
        if (j == qt) {
#pragma unroll
            for (int i = 0; i < 4; i++)
#pragma unroll
                for (int jj = 0; jj < 4; jj++)
                    if (tx * 4 + jj > ty * 4 + i) s[i][jj] = -1e30f;
        }

        // Online softmax update + write P to smem.
#pragma unroll
        for (int i = 0; i < 4; i++) {
            float mt = fmaxf(fmaxf(s[i][0], s[i][1]), fmaxf(s[i][2], s[i][3]));
#pragma unroll
            for (int off = 8; off >= 1; off >>= 1)
                mt = fmaxf(mt, __shfl_xor_sync(0xffffffffu, mt, off));
            float mnew = fmaxf(m[i], mt);
            float corr = __expf(m[i] - mnew);
            float p0 = __expf(s[i][0] - mnew);
            float p1 = __expf(s[i][1] - mnew);
            float p2 = __expf(s[i][2] - mnew);
            float p3 = __expf(s[i][3] - mnew);
            float lp = (p0 + p1) + (p2 + p3);
#pragma unroll
            for (int off = 8; off >= 1; off >>= 1)
                lp += __shfl_xor_sync(0xffffffffu, lp, off);
            l[i] = l[i] * corr + lp;
            m[i] = mnew;
#pragma unroll
            for (int jj = 0; jj < 8; jj++) o[i][jj] *= corr;
            float4 pv = make_float4(p0, p1, p2, p3);
            *(float4*)(&Ps[(ty * 4 + i) * PS_STRIDE + tx * 4]) = pv;
        }
        __syncthreads();

        // O += P @ V  (4x8 per thread; V reads contiguous, P reads broadcast).
#pragma unroll 2
        for (int c = 0; c < 64; c++) {
            float4 v0 = *(const float4*)(&Vs[c * VS_STRIDE + tx * 4]);
            float4 v1 = *(const float4*)(&Vs[c * VS_STRIDE + 64 + tx * 4]);
#pragma unroll
            for (int i = 0; i < 4; i++) {
                float p = Ps[(ty * 4 + i) * PS_STRIDE + c];
                o[i][0] += p * v0.x; o[i][1] += p * v0.y;
                o[i][2] += p * v0.z; o[i][3] += p * v0.w;
                o[i][4] += p * v1.x; o[i][5] += p * v1.y;
                o[i][6] += p * v1.z; o[i][7] += p * v1.w;
            }
        }
    }

    // Normalize and write out[b][t][h].
#pragma unroll
    for (int i = 0; i < 4; i++) {
        float inv = 1.0f / l[i];
        size_t base = ((size_t)b * T_ + q0 + ty * 4 + i) * H_;
        float4 r0 = make_float4(o[i][0] * inv, o[i][1] * inv,
                                o[i][2] * inv, o[i][3] * inv);
        float4 r1 = make_float4(o[i][4] * inv, o[i][5] * inv,
                                o[i][6] * inv, o[i][7] * inv);
        *(float4*)(out + base + tx * 4)      = r0;
        *(float4*)(out + base + 64 + tx * 4) = r1;
    }
}

// ---------------------------------------------------------------------------
extern "C" void kernel_launch(void* const* d_in, const int* in_sizes, int n_in,
                              void* d_out, int out_size)
{
    const float* x  = (const float*)d_in[0];
    const float* Wk = (const float*)d_in[1];
    const float* Wq = (const float*)d_in[2];
    const float* Wv = (const float*)d_in[3];
    float* out = (float*)d_out;

    // Idempotent, graph-capture-safe (not a stream op).
    cudaFuncSetAttribute(attn_kernel,
                         cudaFuncAttributeMaxDynamicSharedMemorySize, ATTN_SMEM);

    proj_kernel<<<dim3(M_ / 64, 3), 256>>>(x, Wk, Wq, Wv);
    attn_kernel<<<dim3(T_ / 64, B_), 256, ATTN_SMEM>>>(out);
}

// round 3
// speedup vs baseline: 1.2688x; 1.2688x over previous
#include <cuda_runtime.h>
#include <cuda_bf16.h>
#include <cstdint>
#include <math.h>

// Problem shape (fixed by the reference).
#define B_ 8
#define T_ 2048
#define C_ 1024
#define H_ 128
#define M_ (B_ * T_)   // 16384 rows for the projection GEMM

// Scratch (no cudaMalloc allowed -> __device__ globals).
__device__ float g_q[(size_t)M_ * H_];
__device__ float g_k[(size_t)M_ * H_];
__device__ float g_v[(size_t)M_ * H_];
// Split+transposed weights: [t = o*2 + (0=hi,1=lo)][n(128)][k(1024)] bf16 K-major.
__device__ __align__(16) __nv_bfloat16 g_wt[6][128 * 1024];

// ---------------------------------------------------------------------------
// Kernel 0: split + transpose weights into bf16 hi/lo, K-major [n][k].
// ---------------------------------------------------------------------------
__global__ __launch_bounds__(256) void wsplit_kernel(
    const float* __restrict__ Wk, const float* __restrict__ Wq,
    const float* __restrict__ Wv)
{
    int o = blockIdx.y;
    const float* W = (o == 0) ? Wk : (o == 1) ? Wq : Wv;
    int idx = blockIdx.x * 256 + threadIdx.x;       // 0..131071 = n*1024 + k
    int n = idx >> 10, k = idx & 1023;
    float v = W[(size_t)k * H_ + n];
    __nv_bfloat16 hi = __float2bfloat16(v);
    float lo = v - __bfloat162float(hi);
    g_wt[o * 2 + 0][idx] = hi;
    g_wt[o * 2 + 1][idx] = __float2bfloat16(lo);
}

// ---------------------------------------------------------------------------
// Kernel 1: QKV projection via mma.sync (bf16, fp32 accum), 3-term split.
// Grid (M_/128, 3). 256 threads = 8 warps, warp grid 2(M) x 4(N).
// CTA tile: 128(M) x 128(N), K staged 64 at a time from fp32 x (split on the
// fly) and pre-split bf16 weights.
// smem strides: 72 bf16 (=144B) -> fragment LDS banks (4g+q)%32, conflict-free.
// ---------------------------------------------------------------------------
#define AST 72                      // bf16 elements per row in smem
#define A_HI_OFF 0
#define A_LO_OFF (128 * AST * 2)    // 18432 B
#define B_HI_OFF (2 * 128 * AST * 2)
#define B_LO_OFF (3 * 128 * AST * 2)
#define PROJ_SMEM (4 * 128 * AST * 2)   // 73728 B

__device__ __forceinline__ void mma16816(float* d, const uint32_t* a,
                                         const uint32_t* b) {
    asm volatile(
        "mma.sync.aligned.m16n8k16.row.col.f32.bf16.bf16.f32 "
        "{%0,%1,%2,%3}, {%4,%5,%6,%7}, {%8,%9}, {%0,%1,%2,%3};"
        : "+f"(d[0]), "+f"(d[1]), "+f"(d[2]), "+f"(d[3])
        : "r"(a[0]), "r"(a[1]), "r"(a[2]), "r"(a[3]), "r"(b[0]), "r"(b[1]));
}

__global__ __launch_bounds__(256) void proj_mma_kernel(const float* __restrict__ x)
{
    extern __shared__ __align__(16) char smem[];
    const int tid  = threadIdx.x;
    const int wid  = tid >> 5;
    const int lane = tid & 31;
    const int wm   = wid >> 2;          // 0..1  (64-row block)
    const int wn   = wid & 3;           // 0..3  (32-col block)
    const int g    = lane >> 2;         // group id 0..7
    const int q    = lane & 3;          // thread-in-group
    const int row0 = blockIdx.x * 128;
    const int o    = blockIdx.y;

    const __nv_bfloat16* wt_hi = g_wt[o * 2 + 0];
    const __nv_bfloat16* wt_lo = g_wt[o * 2 + 1];
    float* outp = (o == 0) ? g_k : (o == 1) ? g_q : g_v;

    float acc[4][4][4];                 // [m][n][frag]
#pragma unroll
    for (int m = 0; m < 4; m++)
#pragma unroll
        for (int n = 0; n < 4; n++)
#pragma unroll
            for (int r = 0; r < 4; r++) acc[m][n][r] = 0.f;

    for (int s = 0; s < 16; s++) {
        const int k0 = s * 64;
        __syncthreads();   // previous stage consumers done

        // ---- stage A: 128 rows x 64 k fp32 -> bf16 hi/lo in smem ----
#pragma unroll
        for (int i = 0; i < 8; i++) {
            int u = tid + 256 * i;              // 0..2047 float4 slots
            int r = u >> 4, gg = u & 15;        // row, k-group of 4
            float4 f = *(const float4*)(x + (size_t)(row0 + r) * C_ + k0 + gg * 4);
            __nv_bfloat16 h0 = __float2bfloat16(f.x);
            __nv_bfloat16 h1 = __float2bfloat16(f.y);
            __nv_bfloat16 h2 = __float2bfloat16(f.z);
            __nv_bfloat16 h3 = __float2bfloat16(f.w);
            __nv_bfloat162 hA = __halves2bfloat162(h0, h1);
            __nv_bfloat162 hB = __halves2bfloat162(h2, h3);
            __nv_bfloat162 lA = __halves2bfloat162(
                __float2bfloat16(f.x - __bfloat162float(h0)),
                __float2bfloat16(f.y - __bfloat162float(h1)));
            __nv_bfloat162 lB = __halves2bfloat162(
                __float2bfloat16(f.z - __bfloat162float(h2)),
                __float2bfloat16(f.w - __bfloat162float(h3)));
            uint32_t off = (uint32_t)(r * (AST * 2) + gg * 8);
            *(uint2*)(smem + A_HI_OFF + off) =
                make_uint2(*(uint32_t*)&hA, *(uint32_t*)&hB);
            *(uint2*)(smem + A_LO_OFF + off) =
                make_uint2(*(uint32_t*)&lA, *(uint32_t*)&lB);
        }
        // ---- stage B: [128 n][64 k] bf16 hi+lo ----
#pragma unroll
        for (int i = 0; i < 8; i++) {
            int u = tid + 256 * i;              // 0..2047 uint4 slots
            int t = u >> 10;                    // 0 hi, 1 lo
            int w = u & 1023;
            int n = w >> 3, gg = w & 7;         // n row, k-group of 8
            const __nv_bfloat16* src = (t == 0) ? wt_hi : wt_lo;
            uint4 v = *(const uint4*)(src + (size_t)n * C_ + k0 + gg * 8);
            uint32_t off = (uint32_t)(n * (AST * 2) + gg * 16);
            char* dst = smem + ((t == 0) ? B_HI_OFF : B_LO_OFF) + off;
            *(uint2*)(dst + 0) = make_uint2(v.x, v.y);
            *(uint2*)(dst + 8) = make_uint2(v.z, v.w);
        }
        __syncthreads();

        // ---- compute: 3 split passes x 4 k-steps of 16 x 16 mmas ----
#pragma unroll
        for (int p = 0; p < 3; p++) {
            const char* sA = smem + ((p == 2) ? A_LO_OFF : A_HI_OFF);
            const char* sB = smem + ((p == 1) ? B_LO_OFF : B_HI_OFF);
#pragma unroll
            for (int kk = 0; kk < 4; kk++) {
                const uint32_t kb = kk * 32 + q * 4;   // byte offset of k-pair
                uint32_t af[4][4];
#pragma unroll
                for (int m = 0; m < 4; m++) {
                    const char* ra =
                        sA + (uint32_t)((wm * 64 + m * 16 + g) * (AST * 2)) + kb;
                    af[m][0] = *(const uint32_t*)(ra);
                    af[m][1] = *(const uint32_t*)(ra + 8 * (AST * 2));
                    af[m][2] = *(const uint32_t*)(ra + 16);
                    af[m][3] = *(const uint32_t*)(ra + 8 * (AST * 2) + 16);
                }
                uint32_t bf[4][2];
#pragma unroll
                for (int n = 0; n < 4; n++) {
                    const char* rb =
                        sB + (uint32_t)((wn * 32 + n * 8 + g) * (AST * 2)) + kb;
                    bf[n][0] = *(const uint32_t*)(rb);
                    bf[n][1] = *(const uint32_t*)(rb + 16);
                }
#pragma unroll
                for (int m = 0; m < 4; m++)
#pragma unroll
                    for (int n = 0; n < 4; n++)
                        mma16816(acc[m][n], af[m], bf[n]);
            }
        }
    }

    // ---- epilogue: fp32 float2 stores straight to gmem ----
#pragma unroll
    for (int m = 0; m < 4; m++) {
        int r0 = row0 + wm * 64 + m * 16 + g;
#pragma unroll
        for (int n = 0; n < 4; n++) {
            int col = wn * 32 + n * 8 + q * 2;
            *(float2*)(outp + (size_t)r0 * H_ + col) =
                make_float2(acc[m][n][0], acc[m][n][1]);
            *(float2*)(outp + (size_t)(r0 + 8) * H_ + col) =
                make_float2(acc[m][n][2], acc[m][n][3]);
        }
    }
}

// ---------------------------------------------------------------------------
// Kernel 2: causal flash attention (unchanged; known-good fp32 SIMT).
// ---------------------------------------------------------------------------
#define QS_STRIDE 132
#define KT_STRIDE 65
#define VS_STRIDE 128
#define PS_STRIDE 68
#define ATTN_SMEM ((64 * QS_STRIDE + 128 * KT_STRIDE + 64 * VS_STRIDE + 64 * PS_STRIDE) * 4)

__global__ __launch_bounds__(256) void attn_kernel(float* __restrict__ out)
{
    extern __shared__ float sm[];
    float* Qs  = sm;
    float* Kst = Qs + 64 * QS_STRIDE;
    float* Vs  = Kst + 128 * KT_STRIDE;
    float* Ps  = Vs + 64 * VS_STRIDE;

    const int b   = blockIdx.y;
    const int qt  = blockIdx.x;
    const int q0  = qt * 64;
    const int tid = threadIdx.x;
    const int tx  = tid & 15;
    const int ty  = tid >> 4;

    const float* qg = g_q + ((size_t)b * T_ + q0) * H_;
#pragma unroll
    for (int i = 0; i < 8; i++) {
        int idx = tid + 256 * i;
        int r = idx >> 5, h4 = idx & 31;
        float4 v = *(const float4*)(qg + (size_t)r * H_ + h4 * 4);
        v.x *= 0.03125f; v.y *= 0.03125f; v.z *= 0.03125f; v.w *= 0.03125f;
        *(float4*)(&Qs[r * QS_STRIDE + h4 * 4]) = v;
    }

    float m[4], l[4], o[4][8];
#pragma unroll
    for (int i = 0; i < 4; i++) {
        m[i] = -1e30f; l[i] = 0.f;
#pragma unroll
        for (int j = 0; j < 8; j++) o[i][j] = 0.f;
    }

    for (int j = 0; j <= qt; j++) {
        const int kv0 = j * 64;
        const float* kg = g_k + ((size_t)b * T_ + kv0) * H_;
        const float* vg = g_v + ((size_t)b * T_ + kv0) * H_;

        __syncthreads();
        {
            int h4 = tid & 31;
            int cb = tid >> 5;
#pragma unroll
            for (int cc = 0; cc < 8; cc++) {
                int c = cb + cc * 8;
                float4 kv = *(const float4*)(kg + (size_t)c * H_ + h4 * 4);
                Kst[(h4 * 4 + 0) * KT_STRIDE + c] = kv.x;
                Kst[(h4 * 4 + 1) * KT_STRIDE + c] = kv.y;
                Kst[(h4 * 4 + 2) * KT_STRIDE + c] = kv.z;
                Kst[(h4 * 4 + 3) * KT_STRIDE + c] = kv.w;
            }
        }
#pragma unroll
        for (int i = 0; i < 8; i++) {
            int idx = tid + 256 * i;
            int r = idx >> 5, h4 = idx & 31;
            *(float4*)(&Vs[r * VS_STRIDE + h4 * 4]) =
                *(const float4*)(vg + (size_t)r * H_ + h4 * 4);
        }
        __syncthreads();

        float s[4][4];
#pragma unroll
        for (int i = 0; i < 4; i++)
#pragma unroll
            for (int jj = 0; jj < 4; jj++) s[i][jj] = 0.f;

#pragma unroll 4
        for (int h = 0; h < 128; h++) {
            float qv[4], kv[4];
#pragma unroll
            for (int i = 0; i < 4; i++)
                qv[i] = Qs[(ty * 4 + i) * QS_STRIDE + h];
#pragma unroll
            for (int jj = 0; jj < 4; jj++)
                kv[jj] = Kst[h * KT_STRIDE + tx * 4 + jj];
#pragma unroll
            for (int i = 0; i < 4; i++)
#pragma unroll
                for (int jj = 0; jj < 4; jj++)
                    s[i][jj] += qv[i] * kv[jj];
        }

        if (j == qt) {
#pragma unroll
            for (int i = 0; i < 4; i++)
#pragma unroll
                for (int jj = 0; jj < 4; jj++)
                    if (tx * 4 + jj > ty * 4 + i) s[i][jj] = -1e30f;
        }

#pragma unroll
        for (int i = 0; i < 4; i++) {
            float mt = fmaxf(fmaxf(s[i][0], s[i][1]), fmaxf(s[i][2], s[i][3]));
#pragma unroll
            for (int off = 8; off >= 1; off >>= 1)
                mt = fmaxf(mt, __shfl_xor_sync(0xffffffffu, mt, off));
            float mnew = fmaxf(m[i], mt);
            float corr = __expf(m[i] - mnew);
            float p0 = __expf(s[i][0] - mnew);
            float p1 = __expf(s[i][1] - mnew);
            float p2 = __expf(s[i][2] - mnew);
            float p3 = __expf(s[i][3] - mnew);
            float lp = (p0 + p1) + (p2 + p3);
#pragma unroll
            for (int off = 8; off >= 1; off >>= 1)
                lp += __shfl_xor_sync(0xffffffffu, lp, off);
            l[i] = l[i] * corr + lp;
            m[i] = mnew;
#pragma unroll
            for (int jj = 0; jj < 8; jj++) o[i][jj] *= corr;
            float4 pv = make_float4(p0, p1, p2, p3);
            *(float4*)(&Ps[(ty * 4 + i) * PS_STRIDE + tx * 4]) = pv;
        }
        __syncthreads();

#pragma unroll 2
        for (int c = 0; c < 64; c++) {
            float4 v0 = *(const float4*)(&Vs[c * VS_STRIDE + tx * 4]);
            float4 v1 = *(const float4*)(&Vs[c * VS_STRIDE + 64 + tx * 4]);
#pragma unroll
            for (int i = 0; i < 4; i++) {
                float p = Ps[(ty * 4 + i) * PS_STRIDE + c];
                o[i][0] += p * v0.x; o[i][1] += p * v0.y;
                o[i][2] += p * v0.z; o[i][3] += p * v0.w;
                o[i][4] += p * v1.x; o[i][5] += p * v1.y;
                o[i][6] += p * v1.z; o[i][7] += p * v1.w;
            }
        }
    }

#pragma unroll
    for (int i = 0; i < 4; i++) {
        float inv = 1.0f / l[i];
        size_t base = ((size_t)b * T_ + q0 + ty * 4 + i) * H_;
        float4 r0 = make_float4(o[i][0] * inv, o[i][1] * inv,
                                o[i][2] * inv, o[i][3] * inv);
        float4 r1 = make_float4(o[i][4] * inv, o[i][5] * inv,
                                o[i][6] * inv, o[i][7] * inv);
        *(float4*)(out + base + tx * 4)      = r0;
        *(float4*)(out + base + 64 + tx * 4) = r1;
    }
}

// ---------------------------------------------------------------------------
extern "C" void kernel_launch(void* const* d_in, const int* in_sizes, int n_in,
                              void* d_out, int out_size)
{
    const float* x  = (const float*)d_in[0];
    const float* Wk = (const float*)d_in[1];
    const float* Wq = (const float*)d_in[2];
    const float* Wv = (const float*)d_in[3];
    float* out = (float*)d_out;

    cudaFuncSetAttribute(proj_mma_kernel,
                         cudaFuncAttributeMaxDynamicSharedMemorySize, PROJ_SMEM);
    cudaFuncSetAttribute(attn_kernel,
                         cudaFuncAttributeMaxDynamicSharedMemorySize, ATTN_SMEM);

    wsplit_kernel<<<dim3(512, 3), 256>>>(Wk, Wq, Wv);
    proj_mma_kernel<<<dim3(128, 3), 256, PROJ_SMEM>>>(x);
    attn_kernel<<<dim3(T_ / 64, B_), 256, ATTN_SMEM>>>(out);
}

// round 6
// speedup vs baseline: 2.3513x; 1.8531x over previous
#include <cuda_runtime.h>
#include <cuda_bf16.h>
#include <cstdint>
#include <math.h>

// Problem shape (fixed by the reference).
#define B_ 8
#define T_ 2048
#define C_ 1024
#define H_ 128
#define M_ (B_ * T_)

// Scratch (no cudaMalloc -> __device__ globals).
// Pre-split bf16 q/k/v (q pre-scaled by 1/32). 6 x 4 MB.
__device__ __align__(16) __nv_bfloat16 g_qh[(size_t)M_ * H_];
__device__ __align__(16) __nv_bfloat16 g_ql[(size_t)M_ * H_];
__device__ __align__(16) __nv_bfloat16 g_kh[(size_t)M_ * H_];
__device__ __align__(16) __nv_bfloat16 g_kl[(size_t)M_ * H_];
__device__ __align__(16) __nv_bfloat16 g_vh[(size_t)M_ * H_];
__device__ __align__(16) __nv_bfloat16 g_vl[(size_t)M_ * H_];
// Split+transposed weights: [t = o*2 + (0=hi,1=lo)][n(128)][k(1024)] bf16 K-major.
__device__ __align__(16) __nv_bfloat16 g_wt[6][128 * 1024];

__device__ __forceinline__ uint32_t pack_bf16(float a, float b) {
    __nv_bfloat162 t = __halves2bfloat162(__float2bfloat16(a), __float2bfloat16(b));
    return *(uint32_t*)&t;
}

__device__ __forceinline__ void mma16816(float* d, const uint32_t* a,
                                         const uint32_t* b) {
    asm volatile(
        "mma.sync.aligned.m16n8k16.row.col.f32.bf16.bf16.f32 "
        "{%0,%1,%2,%3}, {%4,%5,%6,%7}, {%8,%9}, {%0,%1,%2,%3};"
        : "+f"(d[0]), "+f"(d[1]), "+f"(d[2]), "+f"(d[3])
        : "r"(a[0]), "r"(a[1]), "r"(a[2]), "r"(a[3]), "r"(b[0]), "r"(b[1]));
}

// ---------------------------------------------------------------------------
// Kernel 0: split + transpose weights into bf16 hi/lo, K-major [n][k].
// ---------------------------------------------------------------------------
__global__ __launch_bounds__(256) void wsplit_kernel(
    const float* __restrict__ Wk, const float* __restrict__ Wq,
    const float* __restrict__ Wv)
{
    int o = blockIdx.y;
    const float* W = (o == 0) ? Wk : (o == 1) ? Wq : Wv;
    int idx = blockIdx.x * 256 + threadIdx.x;
    int n = idx >> 10, k = idx & 1023;
    float v = W[(size_t)k * H_ + n];
    __nv_bfloat16 hi = __float2bfloat16(v);
    float lo = v - __bfloat162float(hi);
    g_wt[o * 2 + 0][idx] = hi;
    g_wt[o * 2 + 1][idx] = __float2bfloat16(lo);
}

// ---------------------------------------------------------------------------
// Kernel 1: QKV projection via mma.sync (bf16, fp32 accum), 3-term split.
// Epilogue writes PRE-SPLIT bf16 hi/lo (q scaled by 1/32).
// smem rows hold 64 K-elements -> stride 144 B (72 bf16).
// ---------------------------------------------------------------------------
#define AST 72
#define A_HI_OFF 0
#define A_LO_OFF (128 * AST * 2)
#define B_HI_OFF (2 * 128 * AST * 2)
#define B_LO_OFF (3 * 128 * AST * 2)
#define PROJ_SMEM (4 * 128 * AST * 2)

__global__ __launch_bounds__(256) void proj_mma_kernel(const float* __restrict__ x)
{
    extern __shared__ __align__(16) char smem[];
    const int tid  = threadIdx.x;
    const int wid  = tid >> 5;
    const int lane = tid & 31;
    const int wm   = wid >> 2;
    const int wn   = wid & 3;
    const int g    = lane >> 2;
    const int q    = lane & 3;
    const int row0 = blockIdx.x * 128;
    const int o    = blockIdx.y;

    const __nv_bfloat16* wt_hi = g_wt[o * 2 + 0];
    const __nv_bfloat16* wt_lo = g_wt[o * 2 + 1];

    float acc[4][4][4];
#pragma unroll
    for (int m = 0; m < 4; m++)
#pragma unroll
        for (int n = 0; n < 4; n++)
#pragma unroll
            for (int r = 0; r < 4; r++) acc[m][n][r] = 0.f;

    for (int s = 0; s < 16; s++) {
        const int k0 = s * 64;
        __syncthreads();

#pragma unroll
        for (int i = 0; i < 8; i++) {
            int u = tid + 256 * i;
            int r = u >> 4, gg = u & 15;
            float4 f = *(const float4*)(x + (size_t)(row0 + r) * C_ + k0 + gg * 4);
            __nv_bfloat16 h0 = __float2bfloat16(f.x);
            __nv_bfloat16 h1 = __float2bfloat16(f.y);
            __nv_bfloat16 h2 = __float2bfloat16(f.z);
            __nv_bfloat16 h3 = __float2bfloat16(f.w);
            __nv_bfloat162 hA = __halves2bfloat162(h0, h1);
            __nv_bfloat162 hB = __halves2bfloat162(h2, h3);
            __nv_bfloat162 lA = __halves2bfloat162(
                __float2bfloat16(f.x - __bfloat162float(h0)),
                __float2bfloat16(f.y - __bfloat162float(h1)));
            __nv_bfloat162 lB = __halves2bfloat162(
                __float2bfloat16(f.z - __bfloat162float(h2)),
                __float2bfloat16(f.w - __bfloat162float(h3)));
            uint32_t off = (uint32_t)(r * (AST * 2) + gg * 8);
            *(uint2*)(smem + A_HI_OFF + off) =
                make_uint2(*(uint32_t*)&hA, *(uint32_t*)&hB);
            *(uint2*)(smem + A_LO_OFF + off) =
                make_uint2(*(uint32_t*)&lA, *(uint32_t*)&lB);
        }
#pragma unroll
        for (int i = 0; i < 8; i++) {
            int u = tid + 256 * i;
            int t = u >> 10;
            int w = u & 1023;
            int n = w >> 3, gg = w & 7;
            const __nv_bfloat16* src = (t == 0) ? wt_hi : wt_lo;
            uint4 v = *(const uint4*)(src + (size_t)n * C_ + k0 + gg * 8);
            uint32_t off = (uint32_t)(n * (AST * 2) + gg * 16);
            char* dst = smem + ((t == 0) ? B_HI_OFF : B_LO_OFF) + off;
            *(uint2*)(dst + 0) = make_uint2(v.x, v.y);
            *(uint2*)(dst + 8) = make_uint2(v.z, v.w);
        }
        __syncthreads();

#pragma unroll
        for (int p = 0; p < 3; p++) {
            const char* sA = smem + ((p == 2) ? A_LO_OFF : A_HI_OFF);
            const char* sB = smem + ((p == 1) ? B_LO_OFF : B_HI_OFF);
#pragma unroll
            for (int kk = 0; kk < 4; kk++) {
                const uint32_t kb = kk * 32 + q * 4;
                uint32_t af[4][4];
#pragma unroll
                for (int m = 0; m < 4; m++) {
                    const char* ra =
                        sA + (uint32_t)((wm * 64 + m * 16 + g) * (AST * 2)) + kb;
                    af[m][0] = *(const uint32_t*)(ra);
                    af[m][1] = *(const uint32_t*)(ra + 8 * (AST * 2));
                    af[m][2] = *(const uint32_t*)(ra + 16);
                    af[m][3] = *(const uint32_t*)(ra + 8 * (AST * 2) + 16);
                }
                uint32_t bf[4][2];
#pragma unroll
                for (int n = 0; n < 4; n++) {
                    const char* rb =
                        sB + (uint32_t)((wn * 32 + n * 8 + g) * (AST * 2)) + kb;
                    bf[n][0] = *(const uint32_t*)(rb);
                    bf[n][1] = *(const uint32_t*)(rb + 16);
                }
#pragma unroll
                for (int m = 0; m < 4; m++)
#pragma unroll
                    for (int n = 0; n < 4; n++)
                        mma16816(acc[m][n], af[m], bf[n]);
            }
        }
    }

    // Epilogue: split to bf16 hi/lo, q scaled by 1/32.
    const float sc = (o == 1) ? 0.03125f : 1.0f;
    __nv_bfloat16* dh = (o == 0) ? g_kh : (o == 1) ? g_qh : g_vh;
    __nv_bfloat16* dl = (o == 0) ? g_kl : (o == 1) ? g_ql : g_vl;
#pragma unroll
    for (int m = 0; m < 4; m++) {
        int r0 = row0 + wm * 64 + m * 16 + g;
#pragma unroll
        for (int n = 0; n < 4; n++) {
            int col = wn * 32 + n * 8 + q * 2;
            float v0 = acc[m][n][0] * sc, v1 = acc[m][n][1] * sc;
            float v2 = acc[m][n][2] * sc, v3 = acc[m][n][3] * sc;
            __nv_bfloat16 h0 = __float2bfloat16(v0), h1 = __float2bfloat16(v1);
            __nv_bfloat16 h2 = __float2bfloat16(v2), h3 = __float2bfloat16(v3);
            *(uint32_t*)(dh + (size_t)r0 * H_ + col) =
                pack_bf16(__bfloat162float(h0), __bfloat162float(h1));
            *(uint32_t*)(dl + (size_t)r0 * H_ + col) =
                pack_bf16(v0 - __bfloat162float(h0), v1 - __bfloat162float(h1));
            *(uint32_t*)(dh + (size_t)(r0 + 8) * H_ + col) =
                pack_bf16(__bfloat162float(h2), __bfloat162float(h3));
            *(uint32_t*)(dl + (size_t)(r0 + 8) * H_ + col) =
                pack_bf16(v2 - __bfloat162float(h2), v3 - __bfloat162float(h3));
        }
    }
}

// ---------------------------------------------------------------------------
// Kernel 2: causal flash attention on mma.sync bf16 (FA2 style).
// 128 threads = 4 warps, each warp 16 q-rows. Br = Bc = 64, HD = 128.
// Q/K rows: 128 bf16 = 256 B data -> stride 272 B (68 words; 68%32=4, so
// fragment banks are (4g+8kt+q4)%32 -> conflict-free).
// Vt rows: 64 kv = 128 B data -> stride 144 B.
// ---------------------------------------------------------------------------
#define QKS 272
#define VTS 144
#define QH_OFF 0
#define QL_OFF (64 * QKS)            // 17408
#define KH_OFF (2 * 64 * QKS)        // 34816
#define KL_OFF (3 * 64 * QKS)        // 52224
#define VH_OFF (4 * 64 * QKS)        // 69632
#define VL_OFF (4 * 64 * QKS + 128 * VTS)   // 88064
#define ATTN_SMEM (4 * 64 * QKS + 2 * 128 * VTS)  // 106496

__global__ __launch_bounds__(128) void attn_mma_kernel(float* __restrict__ out)
{
    extern __shared__ __align__(16) char smem[];
    const int tid  = threadIdx.x;
    const int w    = tid >> 5;
    const int lane = tid & 31;
    const int g    = lane >> 2;
    const int q4   = lane & 3;

    const int b  = blockIdx.x & 7;
    const int qt = 31 - (blockIdx.x >> 3);   // longest CTAs first
    const int q0 = qt * 64;
    const int bT = b * T_;

    // Stage Q tile (once): 64 rows x 16 uint4.
#pragma unroll
    for (int i = 0; i < 8; i++) {
        int u = tid + 128 * i;
        int r = u >> 4, c = u & 15;
        *(uint4*)(smem + QH_OFF + r * QKS + c * 16) =
            *(const uint4*)(g_qh + (size_t)(bT + q0 + r) * H_ + c * 8);
        *(uint4*)(smem + QL_OFF + r * QKS + c * 16) =
            *(const uint4*)(g_ql + (size_t)(bT + q0 + r) * H_ + c * 8);
    }

    float oacc[16][4];
#pragma unroll
    for (int n = 0; n < 16; n++)
#pragma unroll
        for (int r = 0; r < 4; r++) oacc[n][r] = 0.f;
    float m0 = -1e30f, m1 = -1e30f, l0 = 0.f, l1 = 0.f;

    for (int j = 0; j <= qt; j++) {
        const int kv0 = j * 64;
        __syncthreads();

        // Stage K tile.
#pragma unroll
        for (int i = 0; i < 8; i++) {
            int u = tid + 128 * i;
            int r = u >> 4, c = u & 15;
            *(uint4*)(smem + KH_OFF + r * QKS + c * 16) =
                *(const uint4*)(g_kh + (size_t)(bT + kv0 + r) * H_ + c * 8);
            *(uint4*)(smem + KL_OFF + r * QKS + c * 16) =
                *(const uint4*)(g_kl + (size_t)(bT + kv0 + r) * H_ + c * 8);
        }
        // Stage V transposed: Vt[h][kv], h=0..127, kv pair kv2=0..31.
        // STS banks = (4*(h&7) + (kv2&3)) -> conflict-free.
        const unsigned short* pvh = (const unsigned short*)g_vh;
        const unsigned short* pvl = (const unsigned short*)g_vl;
#pragma unroll
        for (int i = 0; i < 32; i++) {
            int u = tid + 128 * i;
            int h   = (u & 7) | (((u >> 5) & 15) << 3);
            int kv2 = ((u >> 3) & 3) | (((u >> 9) & 7) << 2);
            size_t src = (size_t)(bT + kv0 + kv2 * 2) * H_ + h;
            uint32_t a = pvh[src], bb = pvh[src + H_];
            *(uint32_t*)(smem + VH_OFF + h * VTS + kv2 * 4) = a | (bb << 16);
            a = pvl[src]; bb = pvl[src + H_];
            *(uint32_t*)(smem + VL_OFF + h * VTS + kv2 * 4) = a | (bb << 16);
        }
        __syncthreads();

        // ---- S = Q K^T, 3 split passes ----
        float sacc[8][4];
#pragma unroll
        for (int n = 0; n < 8; n++)
#pragma unroll
            for (int r = 0; r < 4; r++) sacc[n][r] = 0.f;

        const uint32_t arow = (uint32_t)((w * 16 + g) * QKS + q4 * 4);
#pragma unroll
        for (int p = 0; p < 3; p++) {
            const char* sA = smem + ((p == 2) ? QL_OFF : QH_OFF);
            const char* sB = smem + ((p == 1) ? KL_OFF : KH_OFF);
#pragma unroll
            for (int kt = 0; kt < 8; kt++) {
                uint32_t a[4];
                a[0] = *(const uint32_t*)(sA + arow + kt * 32);
                a[1] = *(const uint32_t*)(sA + arow + 8 * QKS + kt * 32);
                a[2] = *(const uint32_t*)(sA + arow + kt * 32 + 16);
                a[3] = *(const uint32_t*)(sA + arow + 8 * QKS + kt * 32 + 16);
#pragma unroll
                for (int n = 0; n < 8; n++) {
                    uint32_t bfr[2];
                    const char* rb = sB + (n * 8 + g) * QKS + kt * 32 + q4 * 4;
                    bfr[0] = *(const uint32_t*)(rb);
                    bfr[1] = *(const uint32_t*)(rb + 16);
                    mma16816(sacc[n], a, bfr);
                }
            }
        }

        // ---- causal mask (diagonal tile only) ----
        if (j == qt) {
            int rl0 = w * 16 + g, rl1 = rl0 + 8;
#pragma unroll
            for (int n = 0; n < 8; n++) {
                int cb = n * 8 + q4 * 2;
                if (cb     > rl0) sacc[n][0] = -1e30f;
                if (cb + 1 > rl0) sacc[n][1] = -1e30f;
                if (cb     > rl1) sacc[n][2] = -1e30f;
                if (cb + 1 > rl1) sacc[n][3] = -1e30f;
            }
        }

        // ---- online softmax ----
        float mx0 = -1e30f, mx1 = -1e30f;
#pragma unroll
        for (int n = 0; n < 8; n++) {
            mx0 = fmaxf(mx0, fmaxf(sacc[n][0], sacc[n][1]));
            mx1 = fmaxf(mx1, fmaxf(sacc[n][2], sacc[n][3]));
        }
        mx0 = fmaxf(mx0, __shfl_xor_sync(0xffffffffu, mx0, 1));
        mx0 = fmaxf(mx0, __shfl_xor_sync(0xffffffffu, mx0, 2));
        mx1 = fmaxf(mx1, __shfl_xor_sync(0xffffffffu, mx1, 1));
        mx1 = fmaxf(mx1, __shfl_xor_sync(0xffffffffu, mx1, 2));
        float mn0 = fmaxf(m0, mx0), mn1 = fmaxf(m1, mx1);
        float c0 = __expf(m0 - mn0), c1 = __expf(m1 - mn1);
        m0 = mn0; m1 = mn1;

        uint32_t ph[8][2], pl[8][2];
        float s0 = 0.f, s1 = 0.f;
#pragma unroll
        for (int n = 0; n < 8; n++) {
            float p00 = __expf(sacc[n][0] - mn0);
            float p01 = __expf(sacc[n][1] - mn0);
            float p10 = __expf(sacc[n][2] - mn1);
            float p11 = __expf(sacc[n][3] - mn1);
            s0 += p00 + p01; s1 += p10 + p11;
            __nv_bfloat16 h00 = __float2bfloat16(p00);
            __nv_bfloat16 h01 = __float2bfloat16(p01);
            __nv_bfloat16 h10 = __float2bfloat16(p10);
            __nv_bfloat16 h11 = __float2bfloat16(p11);
            ph[n][0] = pack_bf16(__bfloat162float(h00), __bfloat162float(h01));
            ph[n][1] = pack_bf16(__bfloat162float(h10), __bfloat162float(h11));
            pl[n][0] = pack_bf16(p00 - __bfloat162float(h00),
                                 p01 - __bfloat162float(h01));
            pl[n][1] = pack_bf16(p10 - __bfloat162float(h10),
                                 p11 - __bfloat162float(h11));
        }
        s0 += __shfl_xor_sync(0xffffffffu, s0, 1);
        s0 += __shfl_xor_sync(0xffffffffu, s0, 2);
        s1 += __shfl_xor_sync(0xffffffffu, s1, 1);
        s1 += __shfl_xor_sync(0xffffffffu, s1, 2);
        l0 = l0 * c0 + s0;
        l1 = l1 * c1 + s1;
#pragma unroll
        for (int n = 0; n < 16; n++) {
            oacc[n][0] *= c0; oacc[n][1] *= c0;
            oacc[n][2] *= c1; oacc[n][3] *= c1;
        }

        // ---- O += P V, 3 split passes (Phi*Vhi, Phi*Vlo, Plo*Vhi) ----
#pragma unroll
        for (int p = 0; p < 3; p++) {
            const char* sV = smem + ((p == 1) ? VL_OFF : VH_OFF);
            const uint32_t (*P)[2] = (p == 2) ? pl : ph;
#pragma unroll
            for (int kt = 0; kt < 4; kt++) {
                uint32_t a[4];
                a[0] = P[2 * kt][0];
                a[1] = P[2 * kt][1];
                a[2] = P[2 * kt + 1][0];
                a[3] = P[2 * kt + 1][1];
#pragma unroll
                for (int n = 0; n < 16; n++) {
                    uint32_t bfr[2];
                    const char* rb = sV + (n * 8 + g) * VTS + kt * 32 + q4 * 4;
                    bfr[0] = *(const uint32_t*)(rb);
                    bfr[1] = *(const uint32_t*)(rb + 16);
                    mma16816(oacc[n], a, bfr);
                }
            }
        }
    }

    // ---- epilogue ----
    float i0 = 1.f / l0, i1 = 1.f / l1;
    size_t rbase = (size_t)(bT + q0 + w * 16 + g);
#pragma unroll
    for (int n = 0; n < 16; n++) {
        int col = n * 8 + q4 * 2;
        *(float2*)(out + rbase * H_ + col) =
            make_float2(oacc[n][0] * i0, oacc[n][1] * i0);
        *(float2*)(out + (rbase + 8) * H_ + col) =
            make_float2(oacc[n][2] * i1, oacc[n][3] * i1);
    }
}

// ---------------------------------------------------------------------------
extern "C" void kernel_launch(void* const* d_in, const int* in_sizes, int n_in,
                              void* d_out, int out_size)
{
    const float* x  = (const float*)d_in[0];
    const float* Wk = (const float*)d_in[1];
    const float* Wq = (const float*)d_in[2];
    const float* Wv = (const float*)d_in[3];
    float* out = (float*)d_out;

    cudaFuncSetAttribute(proj_mma_kernel,
                         cudaFuncAttributeMaxDynamicSharedMemorySize, PROJ_SMEM);
    cudaFuncSetAttribute(attn_mma_kernel,
                         cudaFuncAttributeMaxDynamicSharedMemorySize, ATTN_SMEM);

    wsplit_kernel<<<dim3(512, 3), 256>>>(Wk, Wq, Wv);
    proj_mma_kernel<<<dim3(128, 3), 256, PROJ_SMEM>>>(x);
    attn_mma_kernel<<<256, 128, ATTN_SMEM>>>(out);
}

// round 7
// speedup vs baseline: 2.4777x; 1.0538x over previous
#include <cuda_runtime.h>
#include <cuda_bf16.h>
#include <cstdint>
#include <math.h>

// Problem shape (fixed by the reference).
#define B_ 8
#define T_ 2048
#define C_ 1024
#define H_ 128
#define M_ (B_ * T_)

// Scratch (no cudaMalloc -> __device__ globals).
__device__ __align__(16) __nv_bfloat16 g_qh[(size_t)M_ * H_];
__device__ __align__(16) __nv_bfloat16 g_ql[(size_t)M_ * H_];
__device__ __align__(16) __nv_bfloat16 g_kh[(size_t)M_ * H_];
__device__ __align__(16) __nv_bfloat16 g_kl[(size_t)M_ * H_];
__device__ __align__(16) __nv_bfloat16 g_vh[(size_t)M_ * H_];
__device__ __align__(16) __nv_bfloat16 g_vl[(size_t)M_ * H_];
__device__ __align__(16) __nv_bfloat16 g_wt[6][128 * 1024];

__device__ __forceinline__ uint32_t pack_bf16(float a, float b) {
    __nv_bfloat162 t = __halves2bfloat162(__float2bfloat16(a), __float2bfloat16(b));
    return *(uint32_t*)&t;
}

__device__ __forceinline__ void mma16816(float* d, const uint32_t* a,
                                         const uint32_t* b) {
    asm volatile(
        "mma.sync.aligned.m16n8k16.row.col.f32.bf16.bf16.f32 "
        "{%0,%1,%2,%3}, {%4,%5,%6,%7}, {%8,%9}, {%0,%1,%2,%3};"
        : "+f"(d[0]), "+f"(d[1]), "+f"(d[2]), "+f"(d[3])
        : "r"(a[0]), "r"(a[1]), "r"(a[2]), "r"(a[3]), "r"(b[0]), "r"(b[1]));
}

__device__ __forceinline__ uint32_t cvta_sm(const void* p) {
    uint32_t a;
    asm("{ .reg .u64 t; cvta.to.shared.u64 t, %1; cvt.u32.u64 %0, t; }"
        : "=r"(a) : "l"(p));
    return a;
}
#define LDSM_X4(r0, r1, r2, r3, a)                                        \
    asm volatile("ldmatrix.sync.aligned.m8n8.x4.shared.b16 "              \
                 "{%0,%1,%2,%3}, [%4];"                                   \
                 : "=r"(r0), "=r"(r1), "=r"(r2), "=r"(r3) : "r"(a))
#define LDSM_X4_T(r0, r1, r2, r3, a)                                      \
    asm volatile("ldmatrix.sync.aligned.m8n8.x4.trans.shared.b16 "        \
                 "{%0,%1,%2,%3}, [%4];"                                   \
                 : "=r"(r0), "=r"(r1), "=r"(r2), "=r"(r3) : "r"(a))

// ---------------------------------------------------------------------------
// Kernel 0: split + transpose weights into bf16 hi/lo, K-major [n][k].
// ---------------------------------------------------------------------------
__global__ __launch_bounds__(256) void wsplit_kernel(
    const float* __restrict__ Wk, const float* __restrict__ Wq,
    const float* __restrict__ Wv)
{
    int o = blockIdx.y;
    const float* W = (o == 0) ? Wk : (o == 1) ? Wq : Wv;
    int idx = blockIdx.x * 256 + threadIdx.x;
    int n = idx >> 10, k = idx & 1023;
    float v = W[(size_t)k * H_ + n];
    __nv_bfloat16 hi = __float2bfloat16(v);
    float lo = v - __bfloat162float(hi);
    g_wt[o * 2 + 0][idx] = hi;
    g_wt[o * 2 + 1][idx] = __float2bfloat16(lo);
}

// ---------------------------------------------------------------------------
// Kernel 1: QKV projection via mma.sync (bf16, fp32 accum), 3-term split.
// Unchanged from R6 (passing).
// ---------------------------------------------------------------------------
#define AST 72
#define A_HI_OFF 0
#define A_LO_OFF (128 * AST * 2)
#define B_HI_OFF (2 * 128 * AST * 2)
#define B_LO_OFF (3 * 128 * AST * 2)
#define PROJ_SMEM (4 * 128 * AST * 2)

__global__ __launch_bounds__(256) void proj_mma_kernel(const float* __restrict__ x)
{
    extern __shared__ __align__(16) char smem[];
    const int tid  = threadIdx.x;
    const int wid  = tid >> 5;
    const int lane = tid & 31;
    const int wm   = wid >> 2;
    const int wn   = wid & 3;
    const int g    = lane >> 2;
    const int q    = lane & 3;
    const int row0 = blockIdx.x * 128;
    const int o    = blockIdx.y;

    const __nv_bfloat16* wt_hi = g_wt[o * 2 + 0];
    const __nv_bfloat16* wt_lo = g_wt[o * 2 + 1];

    float acc[4][4][4];
#pragma unroll
    for (int m = 0; m < 4; m++)
#pragma unroll
        for (int n = 0; n < 4; n++)
#pragma unroll
            for (int r = 0; r < 4; r++) acc[m][n][r] = 0.f;

    for (int s = 0; s < 16; s++) {
        const int k0 = s * 64;
        __syncthreads();

#pragma unroll
        for (int i = 0; i < 8; i++) {
            int u = tid + 256 * i;
            int r = u >> 4, gg = u & 15;
            float4 f = *(const float4*)(x + (size_t)(row0 + r) * C_ + k0 + gg * 4);
            __nv_bfloat16 h0 = __float2bfloat16(f.x);
            __nv_bfloat16 h1 = __float2bfloat16(f.y);
            __nv_bfloat16 h2 = __float2bfloat16(f.z);
            __nv_bfloat16 h3 = __float2bfloat16(f.w);
            __nv_bfloat162 hA = __halves2bfloat162(h0, h1);
            __nv_bfloat162 hB = __halves2bfloat162(h2, h3);
            __nv_bfloat162 lA = __halves2bfloat162(
                __float2bfloat16(f.x - __bfloat162float(h0)),
                __float2bfloat16(f.y - __bfloat162float(h1)));
            __nv_bfloat162 lB = __halves2bfloat162(
                __float2bfloat16(f.z - __bfloat162float(h2)),
                __float2bfloat16(f.w - __bfloat162float(h3)));
            uint32_t off = (uint32_t)(r * (AST * 2) + gg * 8);
            *(uint2*)(smem + A_HI_OFF + off) =
                make_uint2(*(uint32_t*)&hA, *(uint32_t*)&hB);
            *(uint2*)(smem + A_LO_OFF + off) =
                make_uint2(*(uint32_t*)&lA, *(uint32_t*)&lB);
        }
#pragma unroll
        for (int i = 0; i < 8; i++) {
            int u = tid + 256 * i;
            int t = u >> 10;
            int w = u & 1023;
            int n = w >> 3, gg = w & 7;
            const __nv_bfloat16* src = (t == 0) ? wt_hi : wt_lo;
            uint4 v = *(const uint4*)(src + (size_t)n * C_ + k0 + gg * 8);
            uint32_t off = (uint32_t)(n * (AST * 2) + gg * 16);
            char* dst = smem + ((t == 0) ? B_HI_OFF : B_LO_OFF) + off;
            *(uint2*)(dst + 0) = make_uint2(v.x, v.y);
            *(uint2*)(dst + 8) = make_uint2(v.z, v.w);
        }
        __syncthreads();

#pragma unroll
        for (int p = 0; p < 3; p++) {
            const char* sA = smem + ((p == 2) ? A_LO_OFF : A_HI_OFF);
            const char* sB = smem + ((p == 1) ? B_LO_OFF : B_HI_OFF);
#pragma unroll
            for (int kk = 0; kk < 4; kk++) {
                const uint32_t kb = kk * 32 + q * 4;
                uint32_t af[4][4];
#pragma unroll
                for (int m = 0; m < 4; m++) {
                    const char* ra =
                        sA + (uint32_t)((wm * 64 + m * 16 + g) * (AST * 2)) + kb;
                    af[m][0] = *(const uint32_t*)(ra);
                    af[m][1] = *(const uint32_t*)(ra + 8 * (AST * 2));
                    af[m][2] = *(const uint32_t*)(ra + 16);
                    af[m][3] = *(const uint32_t*)(ra + 8 * (AST * 2) + 16);
                }
                uint32_t bf[4][2];
#pragma unroll
                for (int n = 0; n < 4; n++) {
                    const char* rb =
                        sB + (uint32_t)((wn * 32 + n * 8 + g) * (AST * 2)) + kb;
                    bf[n][0] = *(const uint32_t*)(rb);
                    bf[n][1] = *(const uint32_t*)(rb + 16);
                }
#pragma unroll
                for (int m = 0; m < 4; m++)
#pragma unroll
                    for (int n = 0; n < 4; n++)
                        mma16816(acc[m][n], af[m], bf[n]);
            }
        }
    }

    const float sc = (o == 1) ? 0.03125f : 1.0f;
    __nv_bfloat16* dh = (o == 0) ? g_kh : (o == 1) ? g_qh : g_vh;
    __nv_bfloat16* dl = (o == 0) ? g_kl : (o == 1) ? g_ql : g_vl;
#pragma unroll
    for (int m = 0; m < 4; m++) {
        int r0 = row0 + wm * 64 + m * 16 + g;
#pragma unroll
        for (int n = 0; n < 4; n++) {
            int col = wn * 32 + n * 8 + q * 2;
            float v0 = acc[m][n][0] * sc, v1 = acc[m][n][1] * sc;
            float v2 = acc[m][n][2] * sc, v3 = acc[m][n][3] * sc;
            __nv_bfloat16 h0 = __float2bfloat16(v0), h1 = __float2bfloat16(v1);
            __nv_bfloat16 h2 = __float2bfloat16(v2), h3 = __float2bfloat16(v3);
            *(uint32_t*)(dh + (size_t)r0 * H_ + col) =
                pack_bf16(__bfloat162float(h0), __bfloat162float(h1));
            *(uint32_t*)(dl + (size_t)r0 * H_ + col) =
                pack_bf16(v0 - __bfloat162float(h0), v1 - __bfloat162float(h1));
            *(uint32_t*)(dh + (size_t)(r0 + 8) * H_ + col) =
                pack_bf16(__bfloat162float(h2), __bfloat162float(h3));
            *(uint32_t*)(dl + (size_t)(r0 + 8) * H_ + col) =
                pack_bf16(v2 - __bfloat162float(h2), v3 - __bfloat162float(h3));
        }
    }
}

// ---------------------------------------------------------------------------
// Kernel 2: causal flash attention, mma.sync bf16 + ldmatrix fragments.
// All tiles row-major, stride 272 B (68 words; rows hit distinct bank groups).
// V stored row-major [kv][h]; P.V B-fragments via ldmatrix.trans.
// smem 104448 B -> 2 CTAs/SM.
// ---------------------------------------------------------------------------
#define QKS 272
#define QH_OFF 0
#define QL_OFF (64 * QKS)
#define KH_OFF (2 * 64 * QKS)
#define KL_OFF (3 * 64 * QKS)
#define VH_OFF (4 * 64 * QKS)
#define VL_OFF (5 * 64 * QKS)
#define ATTN_SMEM (6 * 64 * QKS)   // 104448

__global__ __launch_bounds__(128) void attn_mma_kernel(float* __restrict__ out)
{
    extern __shared__ __align__(16) char smem[];
    const uint32_t sb = cvta_sm(smem);
    const int tid  = threadIdx.x;
    const int w    = tid >> 5;
    const int lane = tid & 31;
    const int g    = lane >> 2;
    const int q4   = lane & 3;

    const int b  = blockIdx.x & 7;
    const int qt = 31 - (blockIdx.x >> 3);   // longest CTAs first
    const int q0 = qt * 64;
    const int bT = b * T_;

    // Per-thread ldmatrix address component: row = lane&15, col-half = lane>>4.
    const uint32_t lm_off = (uint32_t)((lane & 15) * QKS + (lane >> 4) * 16);

    // Stage Q tile (once).
#pragma unroll
    for (int i = 0; i < 8; i++) {
        int u = tid + 128 * i;
        int r = u >> 4, c = u & 15;
        *(uint4*)(smem + QH_OFF + r * QKS + c * 16) =
            *(const uint4*)(g_qh + (size_t)(bT + q0 + r) * H_ + c * 8);
        *(uint4*)(smem + QL_OFF + r * QKS + c * 16) =
            *(const uint4*)(g_ql + (size_t)(bT + q0 + r) * H_ + c * 8);
    }

    float oacc[16][4];
#pragma unroll
    for (int n = 0; n < 16; n++)
#pragma unroll
        for (int r = 0; r < 4; r++) oacc[n][r] = 0.f;
    float m0 = -1e30f, m1 = -1e30f, l0 = 0.f, l1 = 0.f;

    for (int j = 0; j <= qt; j++) {
        const int kv0 = j * 64;
        __syncthreads();

        // Stage K and V tiles (both row-major, coalesced uint4).
#pragma unroll
        for (int i = 0; i < 8; i++) {
            int u = tid + 128 * i;
            int r = u >> 4, c = u & 15;
            size_t src = (size_t)(bT + kv0 + r) * H_ + c * 8;
            uint32_t dst = (uint32_t)(r * QKS + c * 16);
            *(uint4*)(smem + KH_OFF + dst) = *(const uint4*)(g_kh + src);
            *(uint4*)(smem + KL_OFF + dst) = *(const uint4*)(g_kl + src);
            *(uint4*)(smem + VH_OFF + dst) = *(const uint4*)(g_vh + src);
            *(uint4*)(smem + VL_OFF + dst) = *(const uint4*)(g_vl + src);
        }
        __syncthreads();

        // ---- S = Q K^T, 3 split passes, fragments via ldmatrix ----
        float sacc[8][4];
#pragma unroll
        for (int n = 0; n < 8; n++)
#pragma unroll
            for (int r = 0; r < 4; r++) sacc[n][r] = 0.f;

        const uint32_t qrow_off = (uint32_t)(w * 16 * QKS);
#pragma unroll
        for (int p = 0; p < 3; p++) {
            const uint32_t qb = sb + ((p == 2) ? QL_OFF : QH_OFF) + qrow_off + lm_off;
            const uint32_t kb = sb + ((p == 1) ? KL_OFF : KH_OFF) + lm_off;
#pragma unroll
            for (int kt = 0; kt < 8; kt++) {
                uint32_t a[4];
                LDSM_X4(a[0], a[1], a[2], a[3], qb + kt * 32);
#pragma unroll
                for (int nq = 0; nq < 4; nq++) {
                    uint32_t r0, r1, r2, r3;
                    LDSM_X4(r0, r1, r2, r3, kb + nq * 16 * QKS + kt * 32);
                    uint32_t b0[2] = {r0, r2}, b1[2] = {r1, r3};
                    mma16816(sacc[nq * 2], a, b0);
                    mma16816(sacc[nq * 2 + 1], a, b1);
                }
            }
        }

        // ---- causal mask (diagonal tile only) ----
        if (j == qt) {
            int rl0 = w * 16 + g, rl1 = rl0 + 8;
#pragma unroll
            for (int n = 0; n < 8; n++) {
                int cb = n * 8 + q4 * 2;
                if (cb     > rl0) sacc[n][0] = -1e30f;
                if (cb + 1 > rl0) sacc[n][1] = -1e30f;
                if (cb     > rl1) sacc[n][2] = -1e30f;
                if (cb + 1 > rl1) sacc[n][3] = -1e30f;
            }
        }

        // ---- online softmax ----
        float mx0 = -1e30f, mx1 = -1e30f;
#pragma unroll
        for (int n = 0; n < 8; n++) {
            mx0 = fmaxf(mx0, fmaxf(sacc[n][0], sacc[n][1]));
            mx1 = fmaxf(mx1, fmaxf(sacc[n][2], sacc[n][3]));
        }
        mx0 = fmaxf(mx0, __shfl_xor_sync(0xffffffffu, mx0, 1));
        mx0 = fmaxf(mx0, __shfl_xor_sync(0xffffffffu, mx0, 2));
        mx1 = fmaxf(mx1, __shfl_xor_sync(0xffffffffu, mx1, 1));
        mx1 = fmaxf(mx1, __shfl_xor_sync(0xffffffffu, mx1, 2));
        float mn0 = fmaxf(m0, mx0), mn1 = fmaxf(m1, mx1);
        float c0 = __expf(m0 - mn0), c1 = __expf(m1 - mn1);
        m0 = mn0; m1 = mn1;

        uint32_t ph[8][2], pl[8][2];
        float s0 = 0.f, s1 = 0.f;
#pragma unroll
        for (int n = 0; n < 8; n++) {
            float p00 = __expf(sacc[n][0] - mn0);
            float p01 = __expf(sacc[n][1] - mn0);
            float p10 = __expf(sacc[n][2] - mn1);
            float p11 = __expf(sacc[n][3] - mn1);
            s0 += p00 + p01; s1 += p10 + p11;
            __nv_bfloat16 h00 = __float2bfloat16(p00);
            __nv_bfloat16 h01 = __float2bfloat16(p01);
            __nv_bfloat16 h10 = __float2bfloat16(p10);
            __nv_bfloat16 h11 = __float2bfloat16(p11);
            ph[n][0] = pack_bf16(__bfloat162float(h00), __bfloat162float(h01));
            ph[n][1] = pack_bf16(__bfloat162float(h10), __bfloat162float(h11));
            pl[n][0] = pack_bf16(p00 - __bfloat162float(h00),
                                 p01 - __bfloat162float(h01));
            pl[n][1] = pack_bf16(p10 - __bfloat162float(h10),
                                 p11 - __bfloat162float(h11));
        }
        s0 += __shfl_xor_sync(0xffffffffu, s0, 1);
        s0 += __shfl_xor_sync(0xffffffffu, s0, 2);
        s1 += __shfl_xor_sync(0xffffffffu, s1, 1);
        s1 += __shfl_xor_sync(0xffffffffu, s1, 2);
        l0 = l0 * c0 + s0;
        l1 = l1 * c1 + s1;
#pragma unroll
        for (int n = 0; n < 16; n++) {
            oacc[n][0] *= c0; oacc[n][1] *= c0;
            oacc[n][2] *= c1; oacc[n][3] *= c1;
        }

        // ---- O += P V; B-fragments via ldmatrix.trans on row-major V ----
#pragma unroll
        for (int p = 0; p < 3; p++) {
            const uint32_t vb = sb + ((p == 1) ? VL_OFF : VH_OFF) + lm_off;
            const uint32_t (*P)[2] = (p == 2) ? pl : ph;
#pragma unroll
            for (int kt = 0; kt < 4; kt++) {
                uint32_t a[4];
                a[0] = P[2 * kt][0];
                a[1] = P[2 * kt][1];
                a[2] = P[2 * kt + 1][0];
                a[3] = P[2 * kt + 1][1];
#pragma unroll
                for (int np = 0; np < 8; np++) {
                    uint32_t r0, r1, r2, r3;
                    LDSM_X4_T(r0, r1, r2, r3,
                              vb + (uint32_t)(kt * 16 * QKS) + np * 32);
                    uint32_t b0[2] = {r0, r1}, b1[2] = {r2, r3};
                    mma16816(oacc[np * 2], a, b0);
                    mma16816(oacc[np * 2 + 1], a, b1);
                }
            }
        }
    }

    // ---- epilogue ----
    float i0 = 1.f / l0, i1 = 1.f / l1;
    size_t rbase = (size_t)(bT + q0 + w * 16 + g);
#pragma unroll
    for (int n = 0; n < 16; n++) {
        int col = n * 8 + q4 * 2;
        *(float2*)(out + rbase * H_ + col) =
            make_float2(oacc[n][0] * i0, oacc[n][1] * i0);
        *(float2*)(out + (rbase + 8) * H_ + col) =
            make_float2(oacc[n][2] * i1, oacc[n][3] * i1);
    }
}

// ---------------------------------------------------------------------------
extern "C" void kernel_launch(void* const* d_in, const int* in_sizes, int n_in,
                              void* d_out, int out_size)
{
    const float* x  = (const float*)d_in[0];
    const float* Wk = (const float*)d_in[1];
    const float* Wq = (const float*)d_in[2];
    const float* Wv = (const float*)d_in[3];
    float* out = (float*)d_out;

    cudaFuncSetAttribute(proj_mma_kernel,
                         cudaFuncAttributeMaxDynamicSharedMemorySize, PROJ_SMEM);
    cudaFuncSetAttribute(attn_mma_kernel,
                         cudaFuncAttributeMaxDynamicSharedMemorySize, ATTN_SMEM);

    wsplit_kernel<<<dim3(512, 3), 256>>>(Wk, Wq, Wv);
    proj_mma_kernel<<<dim3(128, 3), 256, PROJ_SMEM>>>(x);
    attn_mma_kernel<<<256, 128, ATTN_SMEM>>>(out);
}

// round 9
// speedup vs baseline: 2.4895x; 1.0048x over previous
#include <cuda_runtime.h>
#include <cuda_bf16.h>
#include <cstdint>
#include <math.h>

// Problem shape (fixed by the reference).
#define B_ 8
#define T_ 2048
#define C_ 1024
#define H_ 128
#define M_ (B_ * T_)

// Scratch (no cudaMalloc -> __device__ globals).
__device__ __align__(16) __nv_bfloat16 g_qh[(size_t)M_ * H_];
__device__ __align__(16) __nv_bfloat16 g_ql[(size_t)M_ * H_];
__device__ __align__(16) __nv_bfloat16 g_kh[(size_t)M_ * H_];
__device__ __align__(16) __nv_bfloat16 g_kl[(size_t)M_ * H_];
__device__ __align__(16) __nv_bfloat16 g_vh[(size_t)M_ * H_];
__device__ __align__(16) __nv_bfloat16 g_vl[(size_t)M_ * H_];
__device__ __align__(16) __nv_bfloat16 g_wt[6][128 * 1024];

__device__ __forceinline__ uint32_t pack_bf16(float a, float b) {
    __nv_bfloat162 t = __halves2bfloat162(__float2bfloat16(a), __float2bfloat16(b));
    return *(uint32_t*)&t;
}

__device__ __forceinline__ void mma16816(float* d, const uint32_t* a,
                                         const uint32_t* b) {
    asm volatile(
        "mma.sync.aligned.m16n8k16.row.col.f32.bf16.bf16.f32 "
        "{%0,%1,%2,%3}, {%4,%5,%6,%7}, {%8,%9}, {%0,%1,%2,%3};"
        : "+f"(d[0]), "+f"(d[1]), "+f"(d[2]), "+f"(d[3])
        : "r"(a[0]), "r"(a[1]), "r"(a[2]), "r"(a[3]), "r"(b[0]), "r"(b[1]));
}

__device__ __forceinline__ uint32_t cvta_sm(const void* p) {
    uint32_t a;
    asm("{ .reg .u64 t; cvta.to.shared.u64 t, %1; cvt.u32.u64 %0, t; }"
        : "=r"(a) : "l"(p));
    return a;
}
#define LDSM_X4(r0, r1, r2, r3, a)                                        \
    asm volatile("ldmatrix.sync.aligned.m8n8.x4.shared.b16 "              \
                 "{%0,%1,%2,%3}, [%4];"                                   \
                 : "=r"(r0), "=r"(r1), "=r"(r2), "=r"(r3) : "r"(a))
#define LDSM_X4_T(r0, r1, r2, r3, a)                                      \
    asm volatile("ldmatrix.sync.aligned.m8n8.x4.trans.shared.b16 "        \
                 "{%0,%1,%2,%3}, [%4];"                                   \
                 : "=r"(r0), "=r"(r1), "=r"(r2), "=r"(r3) : "r"(a))

// ---------------------------------------------------------------------------
// Kernel 0: split + transpose weights into bf16 hi/lo, K-major [n][k].
// ---------------------------------------------------------------------------
__global__ __launch_bounds__(256) void wsplit_kernel(
    const float* __restrict__ Wk, const float* __restrict__ Wq,
    const float* __restrict__ Wv)
{
    int o = blockIdx.y;
    const float* W = (o == 0) ? Wk : (o == 1) ? Wq : Wv;
    int idx = blockIdx.x * 256 + threadIdx.x;
    int n = idx >> 10, k = idx & 1023;
    float v = W[(size_t)k * H_ + n];
    __nv_bfloat16 hi = __float2bfloat16(v);
    float lo = v - __bfloat162float(hi);
    g_wt[o * 2 + 0][idx] = hi;
    g_wt[o * 2 + 1][idx] = __float2bfloat16(lo);
}

// ---------------------------------------------------------------------------
// Kernel 1: QKV projection via mma.sync (bf16, fp32 accum), 3-term split.
// Unchanged from R6 (passing).
// ---------------------------------------------------------------------------
#define AST 72
#define A_HI_OFF 0
#define A_LO_OFF (128 * AST * 2)
#define B_HI_OFF (2 * 128 * AST * 2)
#define B_LO_OFF (3 * 128 * AST * 2)
#define PROJ_SMEM (4 * 128 * AST * 2)

__global__ __launch_bounds__(256) void proj_mma_kernel(const float* __restrict__ x)
{
    extern __shared__ __align__(16) char smem[];
    const int tid  = threadIdx.x;
    const int wid  = tid >> 5;
    const int lane = tid & 31;
    const int wm   = wid >> 2;
    const int wn   = wid & 3;
    const int g    = lane >> 2;
    const int q    = lane & 3;
    const int row0 = blockIdx.x * 128;
    const int o    = blockIdx.y;

    const __nv_bfloat16* wt_hi = g_wt[o * 2 + 0];
    const __nv_bfloat16* wt_lo = g_wt[o * 2 + 1];

    float acc[4][4][4];
#pragma unroll
    for (int m = 0; m < 4; m++)
#pragma unroll
        for (int n = 0; n < 4; n++)
#pragma unroll
            for (int r = 0; r < 4; r++) acc[m][n][r] = 0.f;

    for (int s = 0; s < 16; s++) {
        const int k0 = s * 64;
        __syncthreads();

#pragma unroll
        for (int i = 0; i < 8; i++) {
            int u = tid + 256 * i;
            int r = u >> 4, gg = u & 15;
            float4 f = *(const float4*)(x + (size_t)(row0 + r) * C_ + k0 + gg * 4);
            __nv_bfloat16 h0 = __float2bfloat16(f.x);
            __nv_bfloat16 h1 = __float2bfloat16(f.y);
            __nv_bfloat16 h2 = __float2bfloat16(f.z);
            __nv_bfloat16 h3 = __float2bfloat16(f.w);
            __nv_bfloat162 hA = __halves2bfloat162(h0, h1);
            __nv_bfloat162 hB = __halves2bfloat162(h2, h3);
            __nv_bfloat162 lA = __halves2bfloat162(
                __float2bfloat16(f.x - __bfloat162float(h0)),
                __float2bfloat16(f.y - __bfloat162float(h1)));
            __nv_bfloat162 lB = __halves2bfloat162(
                __float2bfloat16(f.z - __bfloat162float(h2)),
                __float2bfloat16(f.w - __bfloat162float(h3)));
            uint32_t off = (uint32_t)(r * (AST * 2) + gg * 8);
            *(uint2*)(smem + A_HI_OFF + off) =
                make_uint2(*(uint32_t*)&hA, *(uint32_t*)&hB);
            *(uint2*)(smem + A_LO_OFF + off) =
                make_uint2(*(uint32_t*)&lA, *(uint32_t*)&lB);
        }
#pragma unroll
        for (int i = 0; i < 8; i++) {
            int u = tid + 256 * i;
            int t = u >> 10;
            int w = u & 1023;
            int n = w >> 3, gg = w & 7;
            const __nv_bfloat16* src = (t == 0) ? wt_hi : wt_lo;
            uint4 v = *(const uint4*)(src + (size_t)n * C_ + k0 + gg * 8);
            uint32_t off = (uint32_t)(n * (AST * 2) + gg * 16);
            char* dst = smem + ((t == 0) ? B_HI_OFF : B_LO_OFF) + off;
            *(uint2*)(dst + 0) = make_uint2(v.x, v.y);
            *(uint2*)(dst + 8) = make_uint2(v.z, v.w);
        }
        __syncthreads();

#pragma unroll
        for (int p = 0; p < 3; p++) {
            const char* sA = smem + ((p == 2) ? A_LO_OFF : A_HI_OFF);
            const char* sB = smem + ((p == 1) ? B_LO_OFF : B_HI_OFF);
#pragma unroll
            for (int kk = 0; kk < 4; kk++) {
                const uint32_t kb = kk * 32 + q * 4;
                uint32_t af[4][4];
#pragma unroll
                for (int m = 0; m < 4; m++) {
                    const char* ra =
                        sA + (uint32_t)((wm * 64 + m * 16 + g) * (AST * 2)) + kb;
                    af[m][0] = *(const uint32_t*)(ra);
                    af[m][1] = *(const uint32_t*)(ra + 8 * (AST * 2));
                    af[m][2] = *(const uint32_t*)(ra + 16);
                    af[m][3] = *(const uint32_t*)(ra + 8 * (AST * 2) + 16);
                }
                uint32_t bf[4][2];
#pragma unroll
                for (int n = 0; n < 4; n++) {
                    const char* rb =
                        sB + (uint32_t)((wn * 32 + n * 8 + g) * (AST * 2)) + kb;
                    bf[n][0] = *(const uint32_t*)(rb);
                    bf[n][1] = *(const uint32_t*)(rb + 16);
                }
#pragma unroll
                for (int m = 0; m < 4; m++)
#pragma unroll
                    for (int n = 0; n < 4; n++)
                        mma16816(acc[m][n], af[m], bf[n]);
            }
        }
    }

    const float sc = (o == 1) ? 0.03125f : 1.0f;
    __nv_bfloat16* dh = (o == 0) ? g_kh : (o == 1) ? g_qh : g_vh;
    __nv_bfloat16* dl = (o == 0) ? g_kl : (o == 1) ? g_ql : g_vl;
#pragma unroll
    for (int m = 0; m < 4; m++) {
        int r0 = row0 + wm * 64 + m * 16 + g;
#pragma unroll
        for (int n = 0; n < 4; n++) {
            int col = wn * 32 + n * 8 + q * 2;
            float v0 = acc[m][n][0] * sc, v1 = acc[m][n][1] * sc;
            float v2 = acc[m][n][2] * sc, v3 = acc[m][n][3] * sc;
            __nv_bfloat16 h0 = __float2bfloat16(v0), h1 = __float2bfloat16(v1);
            __nv_bfloat16 h2 = __float2bfloat16(v2), h3 = __float2bfloat16(v3);
            *(uint32_t*)(dh + (size_t)r0 * H_ + col) =
                pack_bf16(__bfloat162float(h0), __bfloat162float(h1));
            *(uint32_t*)(dl + (size_t)r0 * H_ + col) =
                pack_bf16(v0 - __bfloat162float(h0), v1 - __bfloat162float(h1));
            *(uint32_t*)(dh + (size_t)(r0 + 8) * H_ + col) =
                pack_bf16(__bfloat162float(h2), __bfloat162float(h3));
            *(uint32_t*)(dl + (size_t)(r0 + 8) * H_ + col) =
                pack_bf16(v2 - __bfloat162float(h2), v3 - __bfloat162float(h3));
        }
    }
}

// ---------------------------------------------------------------------------
// Kernel 2: causal flash attention, mma.sync bf16 + ldmatrix fragments.
// All tiles row-major, stride 272 B (68 words; rows hit distinct bank groups).
// V stored row-major [kv][h]; P.V B-fragments via ldmatrix.trans.
// smem 104448 B -> 2 CTAs/SM.
// ---------------------------------------------------------------------------
#define QKS 272
#define QH_OFF 0
#define QL_OFF (64 * QKS)
#define KH_OFF (2 * 64 * QKS)
#define KL_OFF (3 * 64 * QKS)
#define VH_OFF (4 * 64 * QKS)
#define VL_OFF (5 * 64 * QKS)
#define ATTN_SMEM (6 * 64 * QKS)   // 104448

__global__ __launch_bounds__(128) void attn_mma_kernel(float* __restrict__ out)
{
    extern __shared__ __align__(16) char smem[];
    const uint32_t sb = cvta_sm(smem);
    const int tid  = threadIdx.x;
    const int w    = tid >> 5;
    const int lane = tid & 31;
    const int g    = lane >> 2;
    const int q4   = lane & 3;

    const int b  = blockIdx.x & 7;
    const int qt = 31 - (blockIdx.x >> 3);   // longest CTAs first
    const int q0 = qt * 64;
    const int bT = b * T_;

    // Per-thread ldmatrix address component: row = lane&15, col-half = lane>>4.
    const uint32_t lm_off = (uint32_t)((lane & 15) * QKS + (lane >> 4) * 16);

    // Stage Q tile (once).
#pragma unroll
    for (int i = 0; i < 8; i++) {
        int u = tid + 128 * i;
        int r = u >> 4, c = u & 15;
        *(uint4*)(smem + QH_OFF + r * QKS + c * 16) =
            *(const uint4*)(g_qh + (size_t)(bT + q0 + r) * H_ + c * 8);
        *(uint4*)(smem + QL_OFF + r * QKS + c * 16) =
            *(const uint4*)(g_ql + (size_t)(bT + q0 + r) * H_ + c * 8);
    }

    float oacc[16][4];
#pragma unroll
    for (int n = 0; n < 16; n++)
#pragma unroll
        for (int r = 0; r < 4; r++) oacc[n][r] = 0.f;
    float m0 = -1e30f, m1 = -1e30f, l0 = 0.f, l1 = 0.f;

    for (int j = 0; j <= qt; j++) {
        const int kv0 = j * 64;
        __syncthreads();

        // Stage K and V tiles (both row-major, coalesced uint4).
#pragma unroll
        for (int i = 0; i < 8; i++) {
            int u = tid + 128 * i;
            int r = u >> 4, c = u & 15;
            size_t src = (size_t)(bT + kv0 + r) * H_ + c * 8;
            uint32_t dst = (uint32_t)(r * QKS + c * 16);
            *(uint4*)(smem + KH_OFF + dst) = *(const uint4*)(g_kh + src);
            *(uint4*)(smem + KL_OFF + dst) = *(const uint4*)(g_kl + src);
            *(uint4*)(smem + VH_OFF + dst) = *(const uint4*)(g_vh + src);
            *(uint4*)(smem + VL_OFF + dst) = *(const uint4*)(g_vl + src);
        }
        __syncthreads();

        // ---- S = Q K^T, 3 split passes, fragments via ldmatrix ----
        float sacc[8][4];
#pragma unroll
        for (int n = 0; n < 8; n++)
#pragma unroll
            for (int r = 0; r < 4; r++) sacc[n][r] = 0.f;

        const uint32_t qrow_off = (uint32_t)(w * 16 * QKS);
#pragma unroll
        for (int p = 0; p < 3; p++) {
            const uint32_t qb = sb + ((p == 2) ? QL_OFF : QH_OFF) + qrow_off + lm_off;
            const uint32_t kb = sb + ((p == 1) ? KL_OFF : KH_OFF) + lm_off;
#pragma unroll
            for (int kt = 0; kt < 8; kt++) {
                uint32_t a[4];
                LDSM_X4(a[0], a[1], a[2], a[3], qb + kt * 32);
#pragma unroll
                for (int nq = 0; nq < 4; nq++) {
                    uint32_t r0, r1, r2, r3;
                    LDSM_X4(r0, r1, r2, r3, kb + nq * 16 * QKS + kt * 32);
                    uint32_t b0[2] = {r0, r2}, b1[2] = {r1, r3};
                    mma16816(sacc[nq * 2], a, b0);
                    mma16816(sacc[nq * 2 + 1], a, b1);
                }
            }
        }

        // ---- causal mask (diagonal tile only) ----
        if (j == qt) {
            int rl0 = w * 16 + g, rl1 = rl0 + 8;
#pragma unroll
            for (int n = 0; n < 8; n++) {
                int cb = n * 8 + q4 * 2;
                if (cb     > rl0) sacc[n][0] = -1e30f;
                if (cb + 1 > rl0) sacc[n][1] = -1e30f;
                if (cb     > rl1) sacc[n][2] = -1e30f;
                if (cb + 1 > rl1) sacc[n][3] = -1e30f;
            }
        }

        // ---- online softmax ----
        float mx0 = -1e30f, mx1 = -1e30f;
#pragma unroll
        for (int n = 0; n < 8; n++) {
            mx0 = fmaxf(mx0, fmaxf(sacc[n][0], sacc[n][1]));
            mx1 = fmaxf(mx1, fmaxf(sacc[n][2], sacc[n][3]));
        }
        mx0 = fmaxf(mx0, __shfl_xor_sync(0xffffffffu, mx0, 1));
        mx0 = fmaxf(mx0, __shfl_xor_sync(0xffffffffu, mx0, 2));
        mx1 = fmaxf(mx1, __shfl_xor_sync(0xffffffffu, mx1, 1));
        mx1 = fmaxf(mx1, __shfl_xor_sync(0xffffffffu, mx1, 2));
        float mn0 = fmaxf(m0, mx0), mn1 = fmaxf(m1, mx1);
        float c0 = __expf(m0 - mn0), c1 = __expf(m1 - mn1);
        m0 = mn0; m1 = mn1;

        uint32_t ph[8][2], pl[8][2];
        float s0 = 0.f, s1 = 0.f;
#pragma unroll
        for (int n = 0; n < 8; n++) {
            float p00 = __expf(sacc[n][0] - mn0);
            float p01 = __expf(sacc[n][1] - mn0);
            float p10 = __expf(sacc[n][2] - mn1);
            float p11 = __expf(sacc[n][3] - mn1);
            s0 += p00 + p01; s1 += p10 + p11;
            __nv_bfloat16 h00 = __float2bfloat16(p00);
            __nv_bfloat16 h01 = __float2bfloat16(p01);
            __nv_bfloat16 h10 = __float2bfloat16(p10);
            __nv_bfloat16 h11 = __float2bfloat16(p11);
            ph[n][0] = pack_bf16(__bfloat162float(h00), __bfloat162float(h01));
            ph[n][1] = pack_bf16(__bfloat162float(h10), __bfloat162float(h11));
            pl[n][0] = pack_bf16(p00 - __bfloat162float(h00),
                                 p01 - __bfloat162float(h01));
            pl[n][1] = pack_bf16(p10 - __bfloat162float(h10),
                                 p11 - __bfloat162float(h11));
        }
        s0 += __shfl_xor_sync(0xffffffffu, s0, 1);
        s0 += __shfl_xor_sync(0xffffffffu, s0, 2);
        s1 += __shfl_xor_sync(0xffffffffu, s1, 1);
        s1 += __shfl_xor_sync(0xffffffffu, s1, 2);
        l0 = l0 * c0 + s0;
        l1 = l1 * c1 + s1;
#pragma unroll
        for (int n = 0; n < 16; n++) {
            oacc[n][0] *= c0; oacc[n][1] *= c0;
            oacc[n][2] *= c1; oacc[n][3] *= c1;
        }

        // ---- O += P V; B-fragments via ldmatrix.trans on row-major V ----
#pragma unroll
        for (int p = 0; p < 3; p++) {
            const uint32_t vb = sb + ((p == 1) ? VL_OFF : VH_OFF) + lm_off;
            const uint32_t (*P)[2] = (p == 2) ? pl : ph;
#pragma unroll
            for (int kt = 0; kt < 4; kt++) {
                uint32_t a[4];
                a[0] = P[2 * kt][0];
                a[1] = P[2 * kt][1];
                a[2] = P[2 * kt + 1][0];
                a[3] = P[2 * kt + 1][1];
#pragma unroll
                for (int np = 0; np < 8; np++) {
                    uint32_t r0, r1, r2, r3;
                    LDSM_X4_T(r0, r1, r2, r3,
                              vb + (uint32_t)(kt * 16 * QKS) + np * 32);
                    uint32_t b0[2] = {r0, r1}, b1[2] = {r2, r3};
                    mma16816(oacc[np * 2], a, b0);
                    mma16816(oacc[np * 2 + 1], a, b1);
                }
            }
        }
    }

    // ---- epilogue ----
    float i0 = 1.f / l0, i1 = 1.f / l1;
    size_t rbase = (size_t)(bT + q0 + w * 16 + g);
#pragma unroll
    for (int n = 0; n < 16; n++) {
        int col = n * 8 + q4 * 2;
        *(float2*)(out + rbase * H_ + col) =
            make_float2(oacc[n][0] * i0, oacc[n][1] * i0);
        *(float2*)(out + (rbase + 8) * H_ + col) =
            make_float2(oacc[n][2] * i1, oacc[n][3] * i1);
    }
}

// ---------------------------------------------------------------------------
extern "C" void kernel_launch(void* const* d_in, const int* in_sizes, int n_in,
                              void* d_out, int out_size)
{
    const float* x  = (const float*)d_in[0];
    const float* Wk = (const float*)d_in[1];
    const float* Wq = (const float*)d_in[2];
    const float* Wv = (const float*)d_in[3];
    float* out = (float*)d_out;

    cudaFuncSetAttribute(proj_mma_kernel,
                         cudaFuncAttributeMaxDynamicSharedMemorySize, PROJ_SMEM);
    cudaFuncSetAttribute(attn_mma_kernel,
                         cudaFuncAttributeMaxDynamicSharedMemorySize, ATTN_SMEM);

    wsplit_kernel<<<dim3(512, 3), 256>>>(Wk, Wq, Wv);
    proj_mma_kernel<<<dim3(128, 3), 256, PROJ_SMEM>>>(x);
    attn_mma_kernel<<<256, 128, ATTN_SMEM>>>(out);
}

// round 10
// speedup vs baseline: 2.7753x; 1.1148x over previous
#include <cuda_runtime.h>
#include <cuda_bf16.h>
#include <cstdint>
#include <math.h>

// Problem shape (fixed by the reference).
#define B_ 8
#define T_ 2048
#define C_ 1024
#define H_ 128
#define M_ (B_ * T_)

// Scratch (no cudaMalloc -> __device__ globals).
__device__ __align__(16) __nv_bfloat16 g_qh[(size_t)M_ * H_];
__device__ __align__(16) __nv_bfloat16 g_ql[(size_t)M_ * H_];
__device__ __align__(16) __nv_bfloat16 g_kh[(size_t)M_ * H_];
__device__ __align__(16) __nv_bfloat16 g_kl[(size_t)M_ * H_];
__device__ __align__(16) __nv_bfloat16 g_vh[(size_t)M_ * H_];
__device__ __align__(16) __nv_bfloat16 g_vl[(size_t)M_ * H_];
__device__ __align__(16) __nv_bfloat16 g_wt[6][128 * 1024];

__device__ __forceinline__ uint32_t pack_bf16(float a, float b) {
    __nv_bfloat162 t = __halves2bfloat162(__float2bfloat16(a), __float2bfloat16(b));
    return *(uint32_t*)&t;
}

__device__ __forceinline__ void mma16816(float* d, const uint32_t* a,
                                         const uint32_t* b) {
    asm volatile(
        "mma.sync.aligned.m16n8k16.row.col.f32.bf16.bf16.f32 "
        "{%0,%1,%2,%3}, {%4,%5,%6,%7}, {%8,%9}, {%0,%1,%2,%3};"
        : "+f"(d[0]), "+f"(d[1]), "+f"(d[2]), "+f"(d[3])
        : "r"(a[0]), "r"(a[1]), "r"(a[2]), "r"(a[3]), "r"(b[0]), "r"(b[1]));
}

__device__ __forceinline__ uint32_t cvta_sm(const void* p) {
    uint32_t a;
    asm("{ .reg .u64 t; cvta.to.shared.u64 t, %1; cvt.u32.u64 %0, t; }"
        : "=r"(a) : "l"(p));
    return a;
}
#define LDSM_X4(r0, r1, r2, r3, a)                                        \
    asm volatile("ldmatrix.sync.aligned.m8n8.x4.shared.b16 "              \
                 "{%0,%1,%2,%3}, [%4];"                                   \
                 : "=r"(r0), "=r"(r1), "=r"(r2), "=r"(r3) : "r"(a))
#define LDSM_X4_T(r0, r1, r2, r3, a)                                      \
    asm volatile("ldmatrix.sync.aligned.m8n8.x4.trans.shared.b16 "        \
                 "{%0,%1,%2,%3}, [%4];"                                   \
                 : "=r"(r0), "=r"(r1), "=r"(r2), "=r"(r3) : "r"(a))
#define CP16(dst, src)                                                    \
    asm volatile("cp.async.cg.shared.global [%0], [%1], 16;"              \
                 :: "r"(dst), "l"(src))
#define CP_COMMIT() asm volatile("cp.async.commit_group;" ::: "memory")
#define CP_WAIT1()  asm volatile("cp.async.wait_group 1;"  ::: "memory")

// ---------------------------------------------------------------------------
// Kernel 0: split + transpose weights into bf16 hi/lo, K-major [n][k].
// ---------------------------------------------------------------------------
__global__ __launch_bounds__(256) void wsplit_kernel(
    const float* __restrict__ Wk, const float* __restrict__ Wq,
    const float* __restrict__ Wv)
{
    int o = blockIdx.y;
    const float* W = (o == 0) ? Wk : (o == 1) ? Wq : Wv;
    int idx = blockIdx.x * 256 + threadIdx.x;
    int n = idx >> 10, k = idx & 1023;
    float v = W[(size_t)k * H_ + n];
    __nv_bfloat16 hi = __float2bfloat16(v);
    float lo = v - __bfloat162float(hi);
    g_wt[o * 2 + 0][idx] = hi;
    g_wt[o * 2 + 1][idx] = __float2bfloat16(lo);
}

// ---------------------------------------------------------------------------
// Kernel 1: QKV projection via mma.sync (bf16, fp32 accum), 3-term split.
// Unchanged (passing, at the HMMA floor).
// ---------------------------------------------------------------------------
#define AST 72
#define A_HI_OFF 0
#define A_LO_OFF (128 * AST * 2)
#define B_HI_OFF (2 * 128 * AST * 2)
#define B_LO_OFF (3 * 128 * AST * 2)
#define PROJ_SMEM (4 * 128 * AST * 2)

__global__ __launch_bounds__(256) void proj_mma_kernel(const float* __restrict__ x)
{
    extern __shared__ __align__(16) char smem[];
    const int tid  = threadIdx.x;
    const int wid  = tid >> 5;
    const int lane = tid & 31;
    const int wm   = wid >> 2;
    const int wn   = wid & 3;
    const int g    = lane >> 2;
    const int q    = lane & 3;
    const int row0 = blockIdx.x * 128;
    const int o    = blockIdx.y;

    const __nv_bfloat16* wt_hi = g_wt[o * 2 + 0];
    const __nv_bfloat16* wt_lo = g_wt[o * 2 + 1];

    float acc[4][4][4];
#pragma unroll
    for (int m = 0; m < 4; m++)
#pragma unroll
        for (int n = 0; n < 4; n++)
#pragma unroll
            for (int r = 0; r < 4; r++) acc[m][n][r] = 0.f;

    for (int s = 0; s < 16; s++) {
        const int k0 = s * 64;
        __syncthreads();

#pragma unroll
        for (int i = 0; i < 8; i++) {
            int u = tid + 256 * i;
            int r = u >> 4, gg = u & 15;
            float4 f = *(const float4*)(x + (size_t)(row0 + r) * C_ + k0 + gg * 4);
            __nv_bfloat16 h0 = __float2bfloat16(f.x);
            __nv_bfloat16 h1 = __float2bfloat16(f.y);
            __nv_bfloat16 h2 = __float2bfloat16(f.z);
            __nv_bfloat16 h3 = __float2bfloat16(f.w);
            __nv_bfloat162 hA = __halves2bfloat162(h0, h1);
            __nv_bfloat162 hB = __halves2bfloat162(h2, h3);
            __nv_bfloat162 lA = __halves2bfloat162(
                __float2bfloat16(f.x - __bfloat162float(h0)),
                __float2bfloat16(f.y - __bfloat162float(h1)));
            __nv_bfloat162 lB = __halves2bfloat162(
                __float2bfloat16(f.z - __bfloat162float(h2)),
                __float2bfloat16(f.w - __bfloat162float(h3)));
            uint32_t off = (uint32_t)(r * (AST * 2) + gg * 8);
            *(uint2*)(smem + A_HI_OFF + off) =
                make_uint2(*(uint32_t*)&hA, *(uint32_t*)&hB);
            *(uint2*)(smem + A_LO_OFF + off) =
                make_uint2(*(uint32_t*)&lA, *(uint32_t*)&lB);
        }
#pragma unroll
        for (int i = 0; i < 8; i++) {
            int u = tid + 256 * i;
            int t = u >> 10;
            int w = u & 1023;
            int n = w >> 3, gg = w & 7;
            const __nv_bfloat16* src = (t == 0) ? wt_hi : wt_lo;
            uint4 v = *(const uint4*)(src + (size_t)n * C_ + k0 + gg * 8);
            uint32_t off = (uint32_t)(n * (AST * 2) + gg * 16);
            char* dst = smem + ((t == 0) ? B_HI_OFF : B_LO_OFF) + off;
            *(uint2*)(dst + 0) = make_uint2(v.x, v.y);
            *(uint2*)(dst + 8) = make_uint2(v.z, v.w);
        }
        __syncthreads();

#pragma unroll
        for (int p = 0; p < 3; p++) {
            const char* sA = smem + ((p == 2) ? A_LO_OFF : A_HI_OFF);
            const char* sB = smem + ((p == 1) ? B_LO_OFF : B_HI_OFF);
#pragma unroll
            for (int kk = 0; kk < 4; kk++) {
                const uint32_t kb = kk * 32 + q * 4;
                uint32_t af[4][4];
#pragma unroll
                for (int m = 0; m < 4; m++) {
                    const char* ra =
                        sA + (uint32_t)((wm * 64 + m * 16 + g) * (AST * 2)) + kb;
                    af[m][0] = *(const uint32_t*)(ra);
                    af[m][1] = *(const uint32_t*)(ra + 8 * (AST * 2));
                    af[m][2] = *(const uint32_t*)(ra + 16);
                    af[m][3] = *(const uint32_t*)(ra + 8 * (AST * 2) + 16);
                }
                uint32_t bf[4][2];
#pragma unroll
                for (int n = 0; n < 4; n++) {
                    const char* rb =
                        sB + (uint32_t)((wn * 32 + n * 8 + g) * (AST * 2)) + kb;
                    bf[n][0] = *(const uint32_t*)(rb);
                    bf[n][1] = *(const uint32_t*)(rb + 16);
                }
#pragma unroll
                for (int m = 0; m < 4; m++)
#pragma unroll
                    for (int n = 0; n < 4; n++)
                        mma16816(acc[m][n], af[m], bf[n]);
            }
        }
    }

    const float sc = (o == 1) ? 0.03125f : 1.0f;
    __nv_bfloat16* dh = (o == 0) ? g_kh : (o == 1) ? g_qh : g_vh;
    __nv_bfloat16* dl = (o == 0) ? g_kl : (o == 1) ? g_ql : g_vl;
#pragma unroll
    for (int m = 0; m < 4; m++) {
        int r0 = row0 + wm * 64 + m * 16 + g;
#pragma unroll
        for (int n = 0; n < 4; n++) {
            int col = wn * 32 + n * 8 + q * 2;
            float v0 = acc[m][n][0] * sc, v1 = acc[m][n][1] * sc;
            float v2 = acc[m][n][2] * sc, v3 = acc[m][n][3] * sc;
            __nv_bfloat16 h0 = __float2bfloat16(v0), h1 = __float2bfloat16(v1);
            __nv_bfloat16 h2 = __float2bfloat16(v2), h3 = __float2bfloat16(v3);
            *(uint32_t*)(dh + (size_t)r0 * H_ + col) =
                pack_bf16(__bfloat162float(h0), __bfloat162float(h1));
            *(uint32_t*)(dl + (size_t)r0 * H_ + col) =
                pack_bf16(v0 - __bfloat162float(h0), v1 - __bfloat162float(h1));
            *(uint32_t*)(dh + (size_t)(r0 + 8) * H_ + col) =
                pack_bf16(__bfloat162float(h2), __bfloat162float(h3));
            *(uint32_t*)(dl + (size_t)(r0 + 8) * H_ + col) =
                pack_bf16(v2 - __bfloat162float(h2), v3 - __bfloat162float(h3));
        }
    }
}

// ---------------------------------------------------------------------------
// Kernel 2: causal flash attention, paired q-tiles + cp.async double buffer.
// CTA(b, p): warps 0-3 own q-tile 31-p ("B"), warps 4-7 own q-tile p ("A").
// Loop j = 0..31-p stages K/V once; tile A computes only while j <= p.
// Work per CTA = 33 tile-units for every p -> perfectly balanced 128-CTA wave.
// ---------------------------------------------------------------------------
#define QKS 272
#define TSZ (64 * QKS)          // 17408 B per 64x128 bf16 tile
#define QBH_OFF 0
#define QBL_OFF (1 * TSZ)
#define QAH_OFF (2 * TSZ)
#define QAL_OFF (3 * TSZ)
#define KV0_OFF (4 * TSZ)       // + buf*4*TSZ + {Kh,Kl,Vh,Vl}*TSZ
#define ATTN_SMEM (12 * TSZ)    // 208896 B

__global__ __launch_bounds__(256) void attn_mma_kernel(float* __restrict__ out)
{
    extern __shared__ __align__(16) char smem[];
    const uint32_t sb = cvta_sm(smem);
    const int tid  = threadIdx.x;
    const int w    = tid >> 5;
    const int wg   = w >> 2;          // 0 = tile B (large), 1 = tile A (small)
    const int wl   = w & 3;
    const int lane = tid & 31;
    const int g    = lane >> 2;
    const int q4   = lane & 3;

    const int b   = blockIdx.x >> 4;
    const int p   = blockIdx.x & 15;
    const int qtB = 31 - p;
    const int qt_own = wg ? p : qtB;
    const int q0_own = qt_own * 64;
    const int bT  = b * T_;

    const uint32_t lm_off = (uint32_t)((lane & 15) * QKS + (lane >> 4) * 16);

    // ---- Stage both Q tiles (once): 4 x 1024 uint4 = 16 per thread ----
#pragma unroll
    for (int i = 0; i < 8; i++) {
        int u = tid + 256 * i;              // 0..2047: 2 tiles x 1024
        int t = u >> 10;                    // 0 = B, 1 = A
        int rem = u & 1023;
        int r = rem >> 4, c = rem & 15;
        int qrow = (t == 0 ? qtB : p) * 64 + r;
        size_t src = (size_t)(bT + qrow) * H_ + c * 8;
        uint32_t dst = (uint32_t)(t * 2 * TSZ + r * QKS + c * 16);
        *(uint4*)(smem + QBH_OFF + dst) = *(const uint4*)(g_qh + src);
        *(uint4*)(smem + QBL_OFF + dst) = *(const uint4*)(g_ql + src);
    }

    // ---- Prologue: cp.async K/V for j=0 into buf 0 ----
    {
        uint32_t dstb = sb + KV0_OFF;
#pragma unroll
        for (int i = 0; i < 4; i++) {
            int u = tid + 256 * i;
            int r = u >> 4, c = u & 15;
            size_t src = (size_t)(bT + r) * H_ + c * 8;
            uint32_t d0 = dstb + (uint32_t)(r * QKS + c * 16);
            CP16(d0 + 0 * TSZ, g_kh + src);
            CP16(d0 + 1 * TSZ, g_kl + src);
            CP16(d0 + 2 * TSZ, g_vh + src);
            CP16(d0 + 3 * TSZ, g_vl + src);
        }
        CP_COMMIT();
    }

    float oacc[16][4];
#pragma unroll
    for (int n = 0; n < 16; n++)
#pragma unroll
        for (int r = 0; r < 4; r++) oacc[n][r] = 0.f;
    float m0 = -1e30f, m1 = -1e30f, l0 = 0.f, l1 = 0.f;

    for (int j = 0; j <= qtB; j++) {
        __syncthreads();   // everyone done computing from buf (j-1)&1

        // Issue loads for j+1 into buf (j+1)&1 (empty group if past end).
        if (j + 1 <= qtB) {
            const int kvn = (j + 1) * 64;
            uint32_t dstb = sb + KV0_OFF + (uint32_t)(((j + 1) & 1) * 4 * TSZ);
#pragma unroll
            for (int i = 0; i < 4; i++) {
                int u = tid + 256 * i;
                int r = u >> 4, c = u & 15;
                size_t src = (size_t)(bT + kvn + r) * H_ + c * 8;
                uint32_t d0 = dstb + (uint32_t)(r * QKS + c * 16);
                CP16(d0 + 0 * TSZ, g_kh + src);
                CP16(d0 + 1 * TSZ, g_kl + src);
                CP16(d0 + 2 * TSZ, g_vh + src);
                CP16(d0 + 3 * TSZ, g_vl + src);
            }
        }
        CP_COMMIT();
        CP_WAIT1();        // buf j&1 ready
        __syncthreads();

        if (wg == 1 && j > p) continue;   // tile A finished; keep syncing

        const uint32_t kvb = (uint32_t)(KV0_OFF + (j & 1) * 4 * TSZ);
        const uint32_t qh_off = wg ? QAH_OFF : QBH_OFF;
        const uint32_t ql_off = wg ? QAL_OFF : QBL_OFF;

        // ---- S = Q K^T, 3 split passes ----
        float sacc[8][4];
#pragma unroll
        for (int n = 0; n < 8; n++)
#pragma unroll
            for (int r = 0; r < 4; r++) sacc[n][r] = 0.f;

        const uint32_t qrow_off = (uint32_t)(wl * 16 * QKS);
#pragma unroll
        for (int ps = 0; ps < 3; ps++) {
            const uint32_t qb = sb + ((ps == 2) ? ql_off : qh_off) + qrow_off + lm_off;
            const uint32_t kb = sb + kvb + ((ps == 1) ? TSZ : 0) + lm_off;
#pragma unroll
            for (int kt = 0; kt < 8; kt++) {
                uint32_t a[4];
                LDSM_X4(a[0], a[1], a[2], a[3], qb + kt * 32);
#pragma unroll
                for (int nq = 0; nq < 4; nq++) {
                    uint32_t r0, r1, r2, r3;
                    LDSM_X4(r0, r1, r2, r3, kb + nq * 16 * QKS + kt * 32);
                    uint32_t b0[2] = {r0, r2}, b1[2] = {r1, r3};
                    mma16816(sacc[nq * 2], a, b0);
                    mma16816(sacc[nq * 2 + 1], a, b1);
                }
            }
        }

        // ---- causal mask (own diagonal tile only) ----
        if (j == qt_own) {
            int rl0 = wl * 16 + g, rl1 = rl0 + 8;
#pragma unroll
            for (int n = 0; n < 8; n++) {
                int cb = n * 8 + q4 * 2;
                if (cb     > rl0) sacc[n][0] = -1e30f;
                if (cb + 1 > rl0) sacc[n][1] = -1e30f;
                if (cb     > rl1) sacc[n][2] = -1e30f;
                if (cb + 1 > rl1) sacc[n][3] = -1e30f;
            }
        }

        // ---- online softmax ----
        float mx0 = -1e30f, mx1 = -1e30f;
#pragma unroll
        for (int n = 0; n < 8; n++) {
            mx0 = fmaxf(mx0, fmaxf(sacc[n][0], sacc[n][1]));
            mx1 = fmaxf(mx1, fmaxf(sacc[n][2], sacc[n][3]));
        }
        mx0 = fmaxf(mx0, __shfl_xor_sync(0xffffffffu, mx0, 1));
        mx0 = fmaxf(mx0, __shfl_xor_sync(0xffffffffu, mx0, 2));
        mx1 = fmaxf(mx1, __shfl_xor_sync(0xffffffffu, mx1, 1));
        mx1 = fmaxf(mx1, __shfl_xor_sync(0xffffffffu, mx1, 2));
        float mn0 = fmaxf(m0, mx0), mn1 = fmaxf(m1, mx1);
        float c0 = __expf(m0 - mn0), c1 = __expf(m1 - mn1);
        m0 = mn0; m1 = mn1;

        uint32_t ph[8][2], pl[8][2];
        float s0 = 0.f, s1 = 0.f;
#pragma unroll
        for (int n = 0; n < 8; n++) {
            float p00 = __expf(sacc[n][0] - mn0);
            float p01 = __expf(sacc[n][1] - mn0);
            float p10 = __expf(sacc[n][2] - mn1);
            float p11 = __expf(sacc[n][3] - mn1);
            s0 += p00 + p01; s1 += p10 + p11;
            __nv_bfloat16 h00 = __float2bfloat16(p00);
            __nv_bfloat16 h01 = __float2bfloat16(p01);
            __nv_bfloat16 h10 = __float2bfloat16(p10);
            __nv_bfloat16 h11 = __float2bfloat16(p11);
            ph[n][0] = pack_bf16(__bfloat162float(h00), __bfloat162float(h01));
            ph[n][1] = pack_bf16(__bfloat162float(h10), __bfloat162float(h11));
            pl[n][0] = pack_bf16(p00 - __bfloat162float(h00),
                                 p01 - __bfloat162float(h01));
            pl[n][1] = pack_bf16(p10 - __bfloat162float(h10),
                                 p11 - __bfloat162float(h11));
        }
        s0 += __shfl_xor_sync(0xffffffffu, s0, 1);
        s0 += __shfl_xor_sync(0xffffffffu, s0, 2);
        s1 += __shfl_xor_sync(0xffffffffu, s1, 1);
        s1 += __shfl_xor_sync(0xffffffffu, s1, 2);
        l0 = l0 * c0 + s0;
        l1 = l1 * c1 + s1;
#pragma unroll
        for (int n = 0; n < 16; n++) {
            oacc[n][0] *= c0; oacc[n][1] *= c0;
            oacc[n][2] *= c1; oacc[n][3] *= c1;
        }

        // ---- O += P V; 3 split passes; V fragments via ldmatrix.trans ----
#pragma unroll
        for (int ps = 0; ps < 3; ps++) {
            const uint32_t vb = sb + kvb + ((ps == 1) ? 3 : 2) * TSZ + lm_off;
            const uint32_t (*P)[2] = (ps == 2) ? pl : ph;
#pragma unroll
            for (int kt = 0; kt < 4; kt++) {
                uint32_t a[4];
                a[0] = P[2 * kt][0];
                a[1] = P[2 * kt][1];
                a[2] = P[2 * kt + 1][0];
                a[3] = P[2 * kt + 1][1];
#pragma unroll
                for (int np = 0; np < 8; np++) {
                    uint32_t r0, r1, r2, r3;
                    LDSM_X4_T(r0, r1, r2, r3,
                              vb + (uint32_t)(kt * 16 * QKS) + np * 32);
                    uint32_t b0[2] = {r0, r1}, b1[2] = {r2, r3};
                    mma16816(oacc[np * 2], a, b0);
                    mma16816(oacc[np * 2 + 1], a, b1);
                }
            }
        }
    }

    // ---- epilogue ----
    float i0 = 1.f / l0, i1 = 1.f / l1;
    size_t rbase = (size_t)(bT + q0_own + wl * 16 + g);
#pragma unroll
    for (int n = 0; n < 16; n++) {
        int col = n * 8 + q4 * 2;
        *(float2*)(out + rbase * H_ + col) =
            make_float2(oacc[n][0] * i0, oacc[n][1] * i0);
        *(float2*)(out + (rbase + 8) * H_ + col) =
            make_float2(oacc[n][2] * i1, oacc[n][3] * i1);
    }
}

// ---------------------------------------------------------------------------
extern "C" void kernel_launch(void* const* d_in, const int* in_sizes, int n_in,
                              void* d_out, int out_size)
{
    const float* x  = (const float*)d_in[0];
    const float* Wk = (const float*)d_in[1];
    const float* Wq = (const float*)d_in[2];
    const float* Wv = (const float*)d_in[3];
    float* out = (float*)d_out;

    cudaFuncSetAttribute(proj_mma_kernel,
                         cudaFuncAttributeMaxDynamicSharedMemorySize, PROJ_SMEM);
    cudaFuncSetAttribute(attn_mma_kernel,
                         cudaFuncAttributeMaxDynamicSharedMemorySize, ATTN_SMEM);

    wsplit_kernel<<<dim3(512, 3), 256>>>(Wk, Wq, Wv);
    proj_mma_kernel<<<dim3(128, 3), 256, PROJ_SMEM>>>(x);
    attn_mma_kernel<<<128, 256, ATTN_SMEM>>>(out);
}